// round 1
// baseline (speedup 1.0000x reference)
#include <cuda_runtime.h>
#include <cstdint>
#include <cstdio>

#define NPTS 16384
#define HID  256
#define NUF  0.01f

static constexpr size_t NEL = (size_t)NPTS * HID;     // elements per channel-matrix
static constexpr int KC  = 32;                        // K chunk
static constexpr int LDA = 66;                        // smem stride for A (floats), even for 8B-aligned f32x2
static constexpr int LDW = 68;                        // smem stride for W (floats), 16B-aligned rows
static constexpr int SMEM_A_FLOATS = 6 * KC * LDA;    // 12672
static constexpr int SMEM_BYTES = (SMEM_A_FLOATS + KC * LDW) * 4;  // 50688 + 8704 = 59392

// Scratch state: 6 channels x [NPTS x 256], ping-pong. Static device arrays (no runtime alloc).
__device__ float g_bufA[6 * NEL];
__device__ float g_bufB[6 * NEL];

__device__ __forceinline__ void ffma2(unsigned long long& d, unsigned long long a, unsigned long long b) {
    asm("fma.rn.f32x2 %0, %1, %2, %0;" : "+l"(d) : "l"(a), "l"(b));
}
__device__ __forceinline__ unsigned long long pack2(float w) {
    unsigned long long r;
    unsigned u = __float_as_uint(w);
    asm("mov.b64 %0, {%1, %1};" : "=l"(r) : "r"(u));
    return r;
}

// ---------------------------------------------------------------------------
// Layer 0: (t,x,y) -> 6-channel state after first sin layer.
// a_j = t*W0[0][j] + x*W0[1][j] + y*W0[2][j] + b0[j]
// seeds: a_t = W0[0][j], a_x = W0[1][j], a_y = W0[2][j], a_xx = a_yy = 0
// ---------------------------------------------------------------------------
__global__ void k_init(const float* __restrict__ t, const float* __restrict__ x,
                       const float* __restrict__ y, const float* __restrict__ W0,
                       const float* __restrict__ b0, float* __restrict__ out) {
    int idx = blockIdx.x * 256 + threadIdx.x;
    int j = idx & 255;
    int i = idx >> 8;
    float w0 = W0[j], w1 = W0[256 + j], w2 = W0[512 + j];
    float a = t[i] * w0 + x[i] * w1 + y[i] * w2 + b0[j];
    float s, c;
    sincosf(a, &s, &c);
    size_t base = (size_t)i * HID + j;
    out[0 * NEL + base] = s;             // h
    out[1 * NEL + base] = c * w0;        // h_t
    out[2 * NEL + base] = c * w1;        // h_x
    out[3 * NEL + base] = c * w2;        // h_y
    out[4 * NEL + base] = -s * w1 * w1;  // h_xx
    out[5 * NEL + base] = -s * w2 * w2;  // h_yy
}

// ---------------------------------------------------------------------------
// Middle layer: 6-channel GEMM [64pts x 64units, K=256] per CTA, fused sin
// epilogue with second-order forward-mode chain rule.
// Thread tile: 2 points (one f32x2 pair) x 8 units x 6 channels = 48 FFMA2/k.
// ---------------------------------------------------------------------------
__global__ __launch_bounds__(256, 1)
void k_mid(const float* __restrict__ in, const float* __restrict__ W,
           const float* __restrict__ b, float* __restrict__ out) {
    extern __shared__ float sm[];
    float* As = sm;                    // [6][KC][LDA]
    float* Ws = sm + SMEM_A_FLOATS;    // [KC][LDW]

    const int tid = threadIdx.x;
    const int tp = tid & 31;   // point-pair index (covers 64 points)
    const int tu = tid >> 5;   // unit group: 8 units each; whole warp shares tu -> W broadcast
    const int i0 = blockIdx.x * 64;
    const int j0 = blockIdx.y * 64;

    unsigned long long acc[6][8];
#pragma unroll
    for (int ch = 0; ch < 6; ch++)
#pragma unroll
        for (int u = 0; u < 8; u++) acc[ch][u] = 0ULL;

    const int kk = (tid & 7) * 4;    // k sub-offset for A loads
    const int rbase = tid >> 3;      // row base for A loads (8 threads/row)
    const int wcol = (tid & 15) * 4; // W col offset
    const int wkb = tid >> 4;        // W row base (16 threads/row)

    for (int kc = 0; kc < HID; kc += KC) {
        __syncthreads();
        // Load A tile (6 ch x 64 pts x 32 k), transposed into smem: As[ch][k][p]
#pragma unroll
        for (int it = 0; it < 12; it++) {
            int r = rbase + it * 32;         // 0..383
            int ch = r >> 6;
            int p = r & 63;
            const float4 v = *reinterpret_cast<const float4*>(
                in + (size_t)ch * NEL + (size_t)(i0 + p) * HID + kc + kk);
            float* dst = As + ch * (KC * LDA) + kk * LDA + p;
            dst[0 * LDA] = v.x;
            dst[1 * LDA] = v.y;
            dst[2 * LDA] = v.z;
            dst[3 * LDA] = v.w;
        }
        // Load W tile (32 k x 64 j)
#pragma unroll
        for (int it = 0; it < 2; it++) {
            int k = wkb + it * 16;
            *reinterpret_cast<float4*>(Ws + k * LDW + wcol) =
                *reinterpret_cast<const float4*>(W + (size_t)(kc + k) * HID + j0 + wcol);
        }
        __syncthreads();

#pragma unroll 8
        for (int k = 0; k < KC; k++) {
            const float4 wlo = *reinterpret_cast<const float4*>(Ws + k * LDW + tu * 8);
            const float4 whi = *reinterpret_cast<const float4*>(Ws + k * LDW + tu * 8 + 4);
            unsigned long long wp[8];
            wp[0] = pack2(wlo.x); wp[1] = pack2(wlo.y); wp[2] = pack2(wlo.z); wp[3] = pack2(wlo.w);
            wp[4] = pack2(whi.x); wp[5] = pack2(whi.y); wp[6] = pack2(whi.z); wp[7] = pack2(whi.w);
#pragma unroll
            for (int ch = 0; ch < 6; ch++) {
                const unsigned long long a2 = *reinterpret_cast<const unsigned long long*>(
                    As + ch * (KC * LDA) + k * LDA + tp * 2);
#pragma unroll
                for (int u = 0; u < 8; u++) ffma2(acc[ch][u], a2, wp[u]);
            }
        }
    }

    // Epilogue: bias + sin chain rule, write activated 6-channel state.
    float bj[8];
#pragma unroll
    for (int u = 0; u < 8; u++) bj[u] = b[j0 + tu * 8 + u];

#pragma unroll
    for (int half = 0; half < 2; half++) {
        const int p = i0 + tp * 2 + half;
        float res[6][8];
#pragma unroll
        for (int u = 0; u < 8; u++) {
            float a[6];
#pragma unroll
            for (int ch = 0; ch < 6; ch++) {
                unsigned long long q = acc[ch][u];
                unsigned w32 = half ? (unsigned)(q >> 32) : (unsigned)(q & 0xFFFFFFFFull);
                a[ch] = __uint_as_float(w32);
            }
            float a0 = a[0] + bj[u];
            float s, c;
            sincosf(a0, &s, &c);
            res[0][u] = s;
            res[1][u] = c * a[1];
            res[2][u] = c * a[2];
            res[3][u] = c * a[3];
            res[4][u] = c * a[4] - s * a[2] * a[2];
            res[5][u] = c * a[5] - s * a[3] * a[3];
        }
#pragma unroll
        for (int ch = 0; ch < 6; ch++) {
            float* o = out + (size_t)ch * NEL + (size_t)p * HID + j0 + tu * 8;
            *reinterpret_cast<float4*>(o)     = make_float4(res[ch][0], res[ch][1], res[ch][2], res[ch][3]);
            *reinterpret_cast<float4*>(o + 4) = make_float4(res[ch][4], res[ch][5], res[ch][6], res[ch][7]);
        }
    }
}

// ---------------------------------------------------------------------------
// Final layer (256 -> 3, linear) + NS residual assembly. One warp per point.
// ---------------------------------------------------------------------------
__global__ void k_final(const float* __restrict__ in, const float* __restrict__ W6,
                        const float* __restrict__ b6, float* __restrict__ out) {
    const int warp = (blockIdx.x * blockDim.x + threadIdx.x) >> 5;
    const int lane = threadIdx.x & 31;
    if (warp >= NPTS) return;

    float acc[6][3];
#pragma unroll
    for (int ch = 0; ch < 6; ch++)
#pragma unroll
        for (int o = 0; o < 3; o++) acc[ch][o] = 0.f;

    for (int k = lane; k < HID; k += 32) {
        const float w0 = W6[k * 3 + 0];
        const float w1 = W6[k * 3 + 1];
        const float w2 = W6[k * 3 + 2];
#pragma unroll
        for (int ch = 0; ch < 6; ch++) {
            const float h = in[(size_t)ch * NEL + (size_t)warp * HID + k];
            acc[ch][0] += h * w0;
            acc[ch][1] += h * w1;
            acc[ch][2] += h * w2;
        }
    }
#pragma unroll
    for (int ch = 0; ch < 6; ch++)
#pragma unroll
        for (int o = 0; o < 3; o++)
#pragma unroll
            for (int off = 16; off; off >>= 1)
                acc[ch][o] += __shfl_xor_sync(0xFFFFFFFFu, acc[ch][o], off);

    if (lane == 0) {
        const float u = acc[0][0] + b6[0];
        const float v = acc[0][1] + b6[1];
        const float ut = acc[1][0], vt = acc[1][1];
        const float ux = acc[2][0], vx = acc[2][1], px = acc[2][2];
        const float uy = acc[3][0], vy = acc[3][1], py = acc[3][2];
        const float uxx = acc[4][0], vxx = acc[4][1];
        const float uyy = acc[5][0], vyy = acc[5][1];
        out[0 * NPTS + warp] = ut + (u * ux + v * uy) + px - NUF * (uxx + uyy);
        out[1 * NPTS + warp] = vt + (u * vx + v * vy) + py - NUF * (vxx + vyy);
        out[2 * NPTS + warp] = ux + vy;
    }
}

// ---------------------------------------------------------------------------
extern "C" void kernel_launch(void* const* d_in, const int* in_sizes, int n_in,
                              void* d_out, int out_size) {
    const float* t  = (const float*)d_in[0];
    const float* x  = (const float*)d_in[1];
    const float* y  = (const float*)d_in[2];
    const float* W0 = (const float*)d_in[3];
    const float* b0 = (const float*)d_in[4];
    const float* W1 = (const float*)d_in[5];
    const float* b1 = (const float*)d_in[6];
    const float* W2 = (const float*)d_in[7];
    const float* b2 = (const float*)d_in[8];
    const float* W3 = (const float*)d_in[9];
    const float* b3 = (const float*)d_in[10];
    const float* W4 = (const float*)d_in[11];
    const float* b4 = (const float*)d_in[12];
    const float* W5 = (const float*)d_in[13];
    const float* b5 = (const float*)d_in[14];
    const float* W6 = (const float*)d_in[15];
    const float* b6 = (const float*)d_in[16];
    float* out = (float*)d_out;

    float *bufA, *bufB;
    cudaGetSymbolAddress((void**)&bufA, g_bufA);
    cudaGetSymbolAddress((void**)&bufB, g_bufB);
    cudaFuncSetAttribute(k_mid, cudaFuncAttributeMaxDynamicSharedMemorySize, SMEM_BYTES);

    k_init<<<NPTS, 256>>>(t, x, y, W0, b0, bufA);
    dim3 g(NPTS / 64, HID / 64);
    k_mid<<<g, 256, SMEM_BYTES>>>(bufA, W1, b1, bufB);
    k_mid<<<g, 256, SMEM_BYTES>>>(bufB, W2, b2, bufA);
    k_mid<<<g, 256, SMEM_BYTES>>>(bufA, W3, b3, bufB);
    k_mid<<<g, 256, SMEM_BYTES>>>(bufB, W4, b4, bufA);
    k_mid<<<g, 256, SMEM_BYTES>>>(bufA, W5, b5, bufB);
    k_final<<<NPTS / 8, 256>>>(bufB, W6, b6, out);
}

// round 2
// speedup vs baseline: 1.0526x; 1.0526x over previous
#include <cuda_runtime.h>
#include <cstdint>
#include <cstdio>

#define NPTS 16384
#define HID  256
#define NUF  0.01f

static constexpr size_t NEL = (size_t)NPTS * HID;     // elements per channel-matrix
static constexpr int KC  = 32;                        // K chunk
static constexpr int LDA = 66;                        // smem stride for A (floats), even for 8B-aligned f32x2
static constexpr int LDW = 68;                        // smem stride for W (floats), 16B-aligned rows
static constexpr int SMEM_A_FLOATS = 6 * KC * LDA;    // 12672
static constexpr int SMEM_BYTES = (SMEM_A_FLOATS + KC * LDW) * 4;  // 50688 + 8704 = 59392

// Scratch state: 6 channels x [NPTS x 256], ping-pong. Static device arrays (no runtime alloc).
__device__ float g_bufA[6 * NEL];
__device__ float g_bufB[6 * NEL];

__device__ __forceinline__ void ffma2(unsigned long long& d, unsigned long long a, unsigned long long b) {
    asm("fma.rn.f32x2 %0, %1, %2, %0;" : "+l"(d) : "l"(a), "l"(b));
}
__device__ __forceinline__ unsigned long long pack2(float w) {
    unsigned long long r;
    unsigned u = __float_as_uint(w);
    asm("mov.b64 %0, {%1, %1};" : "=l"(r) : "r"(u));
    return r;
}

// ---------------------------------------------------------------------------
// Layer 0: (t,x,y) -> 6-channel state after first sin layer.
// a_j = t*W0[0][j] + x*W0[1][j] + y*W0[2][j] + b0[j]
// seeds: a_t = W0[0][j], a_x = W0[1][j], a_y = W0[2][j], a_xx = a_yy = 0
// ---------------------------------------------------------------------------
__global__ void k_init(const float* __restrict__ t, const float* __restrict__ x,
                       const float* __restrict__ y, const float* __restrict__ W0,
                       const float* __restrict__ b0, float* __restrict__ out) {
    int idx = blockIdx.x * 256 + threadIdx.x;
    int j = idx & 255;
    int i = idx >> 8;
    float w0 = W0[j], w1 = W0[256 + j], w2 = W0[512 + j];
    float a = t[i] * w0 + x[i] * w1 + y[i] * w2 + b0[j];
    float s, c;
    sincosf(a, &s, &c);
    size_t base = (size_t)i * HID + j;
    out[0 * NEL + base] = s;             // h
    out[1 * NEL + base] = c * w0;        // h_t
    out[2 * NEL + base] = c * w1;        // h_x
    out[3 * NEL + base] = c * w2;        // h_y
    out[4 * NEL + base] = -s * w1 * w1;  // h_xx
    out[5 * NEL + base] = -s * w2 * w2;  // h_yy
}

// ---------------------------------------------------------------------------
// Middle layer: 6-channel GEMM [64pts x 64units, K=256] per CTA, fused sin
// epilogue with second-order forward-mode chain rule.
// Thread tile: 2 points (one f32x2 pair) x 8 units x 6 channels = 48 FFMA2/k.
// ---------------------------------------------------------------------------
__global__ __launch_bounds__(256, 1)
void k_mid(const float* __restrict__ in, const float* __restrict__ W,
           const float* __restrict__ b, float* __restrict__ out) {
    extern __shared__ float sm[];
    float* As = sm;                    // [6][KC][LDA]
    float* Ws = sm + SMEM_A_FLOATS;    // [KC][LDW]

    const int tid = threadIdx.x;
    const int tp = tid & 31;   // point-pair index (covers 64 points)
    const int tu = tid >> 5;   // unit group: 8 units each; whole warp shares tu -> W broadcast
    const int i0 = blockIdx.x * 64;
    const int j0 = blockIdx.y * 64;

    unsigned long long acc[6][8];
#pragma unroll
    for (int ch = 0; ch < 6; ch++)
#pragma unroll
        for (int u = 0; u < 8; u++) acc[ch][u] = 0ULL;

    const int kk = (tid & 7) * 4;    // k sub-offset for A loads
    const int rbase = tid >> 3;      // row base for A loads (8 threads/row)
    const int wcol = (tid & 15) * 4; // W col offset
    const int wkb = tid >> 4;        // W row base (16 threads/row)

    for (int kc = 0; kc < HID; kc += KC) {
        __syncthreads();
        // Load A tile (6 ch x 64 pts x 32 k), transposed into smem: As[ch][k][p]
#pragma unroll
        for (int it = 0; it < 12; it++) {
            int r = rbase + it * 32;         // 0..383
            int ch = r >> 6;
            int p = r & 63;
            const float4 v = *reinterpret_cast<const float4*>(
                in + (size_t)ch * NEL + (size_t)(i0 + p) * HID + kc + kk);
            float* dst = As + ch * (KC * LDA) + kk * LDA + p;
            dst[0 * LDA] = v.x;
            dst[1 * LDA] = v.y;
            dst[2 * LDA] = v.z;
            dst[3 * LDA] = v.w;
        }
        // Load W tile (32 k x 64 j)
#pragma unroll
        for (int it = 0; it < 2; it++) {
            int k = wkb + it * 16;
            *reinterpret_cast<float4*>(Ws + k * LDW + wcol) =
                *reinterpret_cast<const float4*>(W + (size_t)(kc + k) * HID + j0 + wcol);
        }
        __syncthreads();

#pragma unroll 8
        for (int k = 0; k < KC; k++) {
            const float4 wlo = *reinterpret_cast<const float4*>(Ws + k * LDW + tu * 8);
            const float4 whi = *reinterpret_cast<const float4*>(Ws + k * LDW + tu * 8 + 4);
            unsigned long long wp[8];
            wp[0] = pack2(wlo.x); wp[1] = pack2(wlo.y); wp[2] = pack2(wlo.z); wp[3] = pack2(wlo.w);
            wp[4] = pack2(whi.x); wp[5] = pack2(whi.y); wp[6] = pack2(whi.z); wp[7] = pack2(whi.w);
#pragma unroll
            for (int ch = 0; ch < 6; ch++) {
                const unsigned long long a2 = *reinterpret_cast<const unsigned long long*>(
                    As + ch * (KC * LDA) + k * LDA + tp * 2);
#pragma unroll
                for (int u = 0; u < 8; u++) ffma2(acc[ch][u], a2, wp[u]);
            }
        }
    }

    // Epilogue: bias + sin chain rule, write activated 6-channel state.
    float bj[8];
#pragma unroll
    for (int u = 0; u < 8; u++) bj[u] = b[j0 + tu * 8 + u];

#pragma unroll
    for (int half = 0; half < 2; half++) {
        const int p = i0 + tp * 2 + half;
        float res[6][8];
#pragma unroll
        for (int u = 0; u < 8; u++) {
            float a[6];
#pragma unroll
            for (int ch = 0; ch < 6; ch++) {
                unsigned long long q = acc[ch][u];
                unsigned w32 = half ? (unsigned)(q >> 32) : (unsigned)(q & 0xFFFFFFFFull);
                a[ch] = __uint_as_float(w32);
            }
            float a0 = a[0] + bj[u];
            float s, c;
            sincosf(a0, &s, &c);
            res[0][u] = s;
            res[1][u] = c * a[1];
            res[2][u] = c * a[2];
            res[3][u] = c * a[3];
            res[4][u] = c * a[4] - s * a[2] * a[2];
            res[5][u] = c * a[5] - s * a[3] * a[3];
        }
#pragma unroll
        for (int ch = 0; ch < 6; ch++) {
            float* o = out + (size_t)ch * NEL + (size_t)p * HID + j0 + tu * 8;
            *reinterpret_cast<float4*>(o)     = make_float4(res[ch][0], res[ch][1], res[ch][2], res[ch][3]);
            *reinterpret_cast<float4*>(o + 4) = make_float4(res[ch][4], res[ch][5], res[ch][6], res[ch][7]);
        }
    }
}

// ---------------------------------------------------------------------------
// Final layer (256 -> 3, linear) + NS residual assembly. One warp per point.
// ---------------------------------------------------------------------------
__global__ void k_final(const float* __restrict__ in, const float* __restrict__ W6,
                        const float* __restrict__ b6, float* __restrict__ out) {
    const int warp = (blockIdx.x * blockDim.x + threadIdx.x) >> 5;
    const int lane = threadIdx.x & 31;
    if (warp >= NPTS) return;

    float acc[6][3];
#pragma unroll
    for (int ch = 0; ch < 6; ch++)
#pragma unroll
        for (int o = 0; o < 3; o++) acc[ch][o] = 0.f;

    for (int k = lane; k < HID; k += 32) {
        const float w0 = W6[k * 3 + 0];
        const float w1 = W6[k * 3 + 1];
        const float w2 = W6[k * 3 + 2];
#pragma unroll
        for (int ch = 0; ch < 6; ch++) {
            const float h = in[(size_t)ch * NEL + (size_t)warp * HID + k];
            acc[ch][0] += h * w0;
            acc[ch][1] += h * w1;
            acc[ch][2] += h * w2;
        }
    }
#pragma unroll
    for (int ch = 0; ch < 6; ch++)
#pragma unroll
        for (int o = 0; o < 3; o++)
#pragma unroll
            for (int off = 16; off; off >>= 1)
                acc[ch][o] += __shfl_xor_sync(0xFFFFFFFFu, acc[ch][o], off);

    if (lane == 0) {
        const float u = acc[0][0] + b6[0];
        const float v = acc[0][1] + b6[1];
        const float ut = acc[1][0], vt = acc[1][1];
        const float ux = acc[2][0], vx = acc[2][1], px = acc[2][2];
        const float uy = acc[3][0], vy = acc[3][1], py = acc[3][2];
        const float uxx = acc[4][0], vxx = acc[4][1];
        const float uyy = acc[5][0], vyy = acc[5][1];
        out[0 * NPTS + warp] = ut + (u * ux + v * uy) + px - NUF * (uxx + uyy);
        out[1 * NPTS + warp] = vt + (u * vx + v * vy) + py - NUF * (vxx + vyy);
        out[2 * NPTS + warp] = ux + vy;
    }
}

// ---------------------------------------------------------------------------
extern "C" void kernel_launch(void* const* d_in, const int* in_sizes, int n_in,
                              void* d_out, int out_size) {
    const float* t  = (const float*)d_in[0];
    const float* x  = (const float*)d_in[1];
    const float* y  = (const float*)d_in[2];
    const float* W0 = (const float*)d_in[3];
    const float* b0 = (const float*)d_in[4];
    const float* W1 = (const float*)d_in[5];
    const float* b1 = (const float*)d_in[6];
    const float* W2 = (const float*)d_in[7];
    const float* b2 = (const float*)d_in[8];
    const float* W3 = (const float*)d_in[9];
    const float* b3 = (const float*)d_in[10];
    const float* W4 = (const float*)d_in[11];
    const float* b4 = (const float*)d_in[12];
    const float* W5 = (const float*)d_in[13];
    const float* b5 = (const float*)d_in[14];
    const float* W6 = (const float*)d_in[15];
    const float* b6 = (const float*)d_in[16];
    float* out = (float*)d_out;

    float *bufA, *bufB;
    cudaGetSymbolAddress((void**)&bufA, g_bufA);
    cudaGetSymbolAddress((void**)&bufB, g_bufB);
    cudaFuncSetAttribute(k_mid, cudaFuncAttributeMaxDynamicSharedMemorySize, SMEM_BYTES);

    k_init<<<NPTS, 256>>>(t, x, y, W0, b0, bufA);
    dim3 g(NPTS / 64, HID / 64);
    k_mid<<<g, 256, SMEM_BYTES>>>(bufA, W1, b1, bufB);
    k_mid<<<g, 256, SMEM_BYTES>>>(bufB, W2, b2, bufA);
    k_mid<<<g, 256, SMEM_BYTES>>>(bufA, W3, b3, bufB);
    k_mid<<<g, 256, SMEM_BYTES>>>(bufB, W4, b4, bufA);
    k_mid<<<g, 256, SMEM_BYTES>>>(bufA, W5, b5, bufB);
    k_final<<<NPTS / 8, 256>>>(bufB, W6, b6, out);
}

// round 4
// speedup vs baseline: 1.8285x; 1.7372x over previous
#include <cuda_runtime.h>
#include <cuda_fp16.h>
#include <cstdint>

#define NPTS 16384
#define HID  256
#define NUF  0.01f
static constexpr size_t NEL = (size_t)NPTS * HID;
static constexpr int GRID_M = 6 * NPTS / 128;     // 768 M-tiles
static constexpr float DSC   = 0.0625f;           // derivative-channel storage scale
static constexpr float DSCI  = 16.0f;

// smem stage layout (bytes within one stage)
static constexpr int ST_AH = 0;
static constexpr int ST_AL = 16384;
static constexpr int ST_WH = 32768;
static constexpr int ST_WL = 65536;
static constexpr int STAGE = 98304;
static constexpr int SMEM_BYTES = 2 * STAGE;      // 196608

__device__ __align__(256) __half g_sh[6 * NEL];   // state hi (fp16)
__device__ __align__(256) __half g_sl[6 * NEL];   // state lo (fp16)
__device__ __align__(256) float  g_Z[6 * NEL];    // pre-activation (fp32)
__device__ __align__(256) __half g_wh[5][65536];  // W^T hi, [n][k]
__device__ __align__(256) __half g_wl[5][65536];  // W^T lo, [n][k]

__device__ __forceinline__ uint32_t smem_u32(const void* p) {
    uint32_t a;
    asm("{ .reg .u64 t; cvta.to.shared.u64 t, %1; cvt.u32.u64 %0, t; }" : "=r"(a) : "l"(p));
    return a;
}
__device__ __forceinline__ uint32_t swz(uint32_t o) { return o ^ ((o >> 3) & 0x70); }
__device__ __forceinline__ void cp16(uint32_t dst, const void* src) {
    asm volatile("cp.async.cg.shared.global [%0], [%1], 16;" :: "r"(dst), "l"(src) : "memory");
}
__device__ __forceinline__ void ldsm4(uint32_t* r, uint32_t addr) {
    asm volatile("ldmatrix.sync.aligned.m8n8.x4.shared.b16 {%0,%1,%2,%3}, [%4];"
                 : "=r"(r[0]), "=r"(r[1]), "=r"(r[2]), "=r"(r[3]) : "r"(addr));
}
__device__ __forceinline__ void mma16816(float* c, const uint32_t* a, uint32_t b0, uint32_t b1) {
    asm volatile("mma.sync.aligned.m16n8k16.row.col.f32.f16.f16.f32 "
                 "{%0,%1,%2,%3}, {%4,%5,%6,%7}, {%8,%9}, {%0,%1,%2,%3};"
                 : "+f"(c[0]), "+f"(c[1]), "+f"(c[2]), "+f"(c[3])
                 : "r"(a[0]), "r"(a[1]), "r"(a[2]), "r"(a[3]), "r"(b0), "r"(b1));
}
__device__ __forceinline__ void split16(float x, __half& h, __half& l) {
    h = __float2half_rn(x);
    l = __float2half_rn(x - __half2float(h));
}

// ---------- weight prep: W^T split into fp16 hi/lo ----------
__global__ void k_wprep(const float* W1, const float* W2, const float* W3,
                        const float* W4, const float* W5,
                        __half* __restrict__ wh, __half* __restrict__ wl) {
    int L = blockIdx.y, k = blockIdx.x, n = threadIdx.x;
    const float* W = (L == 0) ? W1 : (L == 1) ? W2 : (L == 2) ? W3 : (L == 3) ? W4 : W5;
    float w = W[k * 256 + n];
    __half h, l;
    split16(w, h, l);
    size_t o = (size_t)L * 65536 + (size_t)n * 256 + k;
    wh[o] = h;
    wl[o] = l;
}

// ---------- layer 0: inputs -> activated 6-channel state (hi/lo fp16) ----------
__global__ void k_init(const float* __restrict__ t, const float* __restrict__ x,
                       const float* __restrict__ y, const float* __restrict__ W0,
                       const float* __restrict__ b0,
                       __half* __restrict__ oh, __half* __restrict__ ol) {
    int i = blockIdx.x, j = threadIdx.x;
    float w0 = W0[j], w1 = W0[256 + j], w2 = W0[512 + j];
    float a = t[i] * w0 + x[i] * w1 + y[i] * w2 + b0[j];
    float s, c;
    sincosf(a, &s, &c);
    float r[6] = {s, c * w0, c * w1, c * w2, -s * w1 * w1, -s * w2 * w2};
    size_t base = (size_t)i * HID + j;
#pragma unroll
    for (int ch = 0; ch < 6; ch++) {
        float v = (ch == 0) ? r[ch] : r[ch] * DSC;   // scale derivative channels
        __half h, l;
        split16(v, h, l);
        oh[(size_t)ch * NEL + base] = h;
        ol[(size_t)ch * NEL + base] = l;
    }
}

// ---------- fp16x3 GEMM: Z[128x256 tile] = state @ W  ----------
__global__ void __launch_bounds__(256, 1)
k_gemm(const __half* __restrict__ Ah, const __half* __restrict__ Al,
       const __half* __restrict__ Wh, const __half* __restrict__ Wl,
       float* __restrict__ Z) {
    extern __shared__ char smem[];
    const uint32_t sb = smem_u32(smem);
    const int tid = threadIdx.x, lane = tid & 31, wid = tid >> 5;
    const int mt = blockIdx.x;
    const int warpM = (wid >> 2) * 64, warpN = (wid & 3) * 64;

    const __half* arh = Ah + (size_t)mt * 128 * 256;
    const __half* arl = Al + (size_t)mt * 128 * 256;

    auto issue = [&](int c, int buf) {
        uint32_t base = sb + buf * STAGE;
#pragma unroll
        for (int m = 0; m < 2; m++) {
            const __half* src = m ? arl : arh;
            uint32_t dstb = base + (m ? ST_AL : ST_AH);
#pragma unroll
            for (int i = 0; i < 4; i++) {
                int idx = tid + i * 256, r = idx >> 3, q = idx & 7;
                cp16(dstb + swz(r * 128 + q * 16), src + (size_t)r * 256 + c * 64 + q * 8);
            }
        }
#pragma unroll
        for (int m = 0; m < 2; m++) {
            const __half* src = m ? Wl : Wh;
            uint32_t dstb = base + (m ? ST_WL : ST_WH);
#pragma unroll
            for (int i = 0; i < 8; i++) {
                int idx = tid + i * 256, n = idx >> 3, q = idx & 7;
                cp16(dstb + swz(n * 128 + q * 16), src + (size_t)n * 256 + c * 64 + q * 8);
            }
        }
        asm volatile("cp.async.commit_group;" ::: "memory");
    };

    float acc[4][8][4];
#pragma unroll
    for (int mi = 0; mi < 4; mi++)
        for (int nj = 0; nj < 8; nj++)
            for (int q = 0; q < 4; q++) acc[mi][nj][q] = 0.f;

    issue(0, 0);
    issue(1, 1);

    const int lr = lane & 7, g = lane >> 3;
    const int roff = (g & 1) * 8 + lr;     // row within 16-row frag
    const int koff = (g >> 1) * 16;        // byte offset within 32B k16 group

    for (int c = 0; c < 4; c++) {
        const int buf = c & 1;
        if (c < 3) asm volatile("cp.async.wait_group 1;" ::: "memory");
        else       asm volatile("cp.async.wait_group 0;" ::: "memory");
        __syncthreads();
        const uint32_t base = sb + buf * STAGE;

#pragma unroll
        for (int ks = 0; ks < 4; ks++) {
            const int kb = ks * 32 + koff;
            uint32_t a_hi[4][4], a_lo[4][4], bq[4][4];
            // B_hi frags (4x ldsm.x4 -> 8 n8-frags)
#pragma unroll
            for (int p = 0; p < 4; p++)
                ldsm4(bq[p], base + ST_WH + swz((warpN + p * 16 + roff) * 128 + kb));
            // A_hi frags
#pragma unroll
            for (int mi = 0; mi < 4; mi++)
                ldsm4(a_hi[mi], base + ST_AH + swz((warpM + mi * 16 + roff) * 128 + kb));
#pragma unroll
            for (int mi = 0; mi < 4; mi++)
#pragma unroll
                for (int p = 0; p < 4; p++) {
                    mma16816(acc[mi][2 * p],     a_hi[mi], bq[p][0], bq[p][2]);
                    mma16816(acc[mi][2 * p + 1], a_hi[mi], bq[p][1], bq[p][3]);
                }
            // A_lo · B_hi
#pragma unroll
            for (int mi = 0; mi < 4; mi++)
                ldsm4(a_lo[mi], base + ST_AL + swz((warpM + mi * 16 + roff) * 128 + kb));
#pragma unroll
            for (int mi = 0; mi < 4; mi++)
#pragma unroll
                for (int p = 0; p < 4; p++) {
                    mma16816(acc[mi][2 * p],     a_lo[mi], bq[p][0], bq[p][2]);
                    mma16816(acc[mi][2 * p + 1], a_lo[mi], bq[p][1], bq[p][3]);
                }
            // A_hi · B_lo  (reuse bq regs)
#pragma unroll
            for (int p = 0; p < 4; p++)
                ldsm4(bq[p], base + ST_WL + swz((warpN + p * 16 + roff) * 128 + kb));
#pragma unroll
            for (int mi = 0; mi < 4; mi++)
#pragma unroll
                for (int p = 0; p < 4; p++) {
                    mma16816(acc[mi][2 * p],     a_hi[mi], bq[p][0], bq[p][2]);
                    mma16816(acc[mi][2 * p + 1], a_hi[mi], bq[p][1], bq[p][3]);
                }
        }
        __syncthreads();
        if (c + 2 < 4) issue(c + 2, buf);
    }

    // epilogue -> Z
    float* zbase = Z + (size_t)mt * 128 * 256;
    const int qr = lane >> 2, qc = (lane & 3) * 2;
#pragma unroll
    for (int mi = 0; mi < 4; mi++) {
        const int r0 = warpM + mi * 16 + qr;
#pragma unroll
        for (int nj = 0; nj < 8; nj++) {
            const int col = warpN + nj * 8 + qc;
            *(float2*)(zbase + (size_t)r0 * 256 + col) =
                make_float2(acc[mi][nj][0], acc[mi][nj][1]);
            *(float2*)(zbase + (size_t)(r0 + 8) * 256 + col) =
                make_float2(acc[mi][nj][2], acc[mi][nj][3]);
        }
    }
}

// ---------- activation: state' = sin-chain(Z + b), write fp16 hi/lo ----------
__global__ void k_act(const float* __restrict__ Zin, const float* __restrict__ b,
                      __half* __restrict__ oh, __half* __restrict__ ol) {
    size_t idx = (size_t)blockIdx.x * 256 + threadIdx.x;
    int j = (int)(idx & 255);
    float a0 = Zin[idx] + __ldg(b + j);
    float a1 = Zin[NEL + idx] * DSCI;
    float a2 = Zin[2 * NEL + idx] * DSCI;
    float a3 = Zin[3 * NEL + idx] * DSCI;
    float a4 = Zin[4 * NEL + idx] * DSCI;
    float a5 = Zin[5 * NEL + idx] * DSCI;
    float s, c;
    sincosf(a0, &s, &c);
    float r[6] = {s, c * a1, c * a2, c * a3,
                  c * a4 - s * a2 * a2, c * a5 - s * a3 * a3};
#pragma unroll
    for (int ch = 0; ch < 6; ch++) {
        float v = (ch == 0) ? r[ch] : r[ch] * DSC;
        __half h, l;
        split16(v, h, l);
        oh[(size_t)ch * NEL + idx] = h;
        ol[(size_t)ch * NEL + idx] = l;
    }
}

// ---------- final layer (256->3) + NS residuals ----------
__global__ void k_final(const __half* __restrict__ ih, const __half* __restrict__ il,
                        const float* __restrict__ W6, const float* __restrict__ b6,
                        float* __restrict__ out) {
    const int warp = (blockIdx.x * blockDim.x + threadIdx.x) >> 5;
    const int lane = threadIdx.x & 31;
    if (warp >= NPTS) return;
    float acc[6][3];
#pragma unroll
    for (int ch = 0; ch < 6; ch++)
        for (int o = 0; o < 3; o++) acc[ch][o] = 0.f;
    for (int k = lane; k < HID; k += 32) {
        float w0 = W6[k * 3], w1 = W6[k * 3 + 1], w2 = W6[k * 3 + 2];
#pragma unroll
        for (int ch = 0; ch < 6; ch++) {
            size_t o = (size_t)ch * NEL + (size_t)warp * HID + k;
            float h = __half2float(ih[o]) + __half2float(il[o]);
            acc[ch][0] += h * w0; acc[ch][1] += h * w1; acc[ch][2] += h * w2;
        }
    }
#pragma unroll
    for (int ch = 0; ch < 6; ch++)
        for (int o = 0; o < 3; o++)
            for (int off = 16; off; off >>= 1)
                acc[ch][o] += __shfl_xor_sync(0xFFFFFFFFu, acc[ch][o], off);
    if (lane == 0) {
        float u = acc[0][0] + b6[0], v = acc[0][1] + b6[1];
        float ut = acc[1][0] * DSCI, vt = acc[1][1] * DSCI;
        float ux = acc[2][0] * DSCI, vx = acc[2][1] * DSCI, px = acc[2][2] * DSCI;
        float uy = acc[3][0] * DSCI, vy = acc[3][1] * DSCI, py = acc[3][2] * DSCI;
        float uxx = acc[4][0] * DSCI, vxx = acc[4][1] * DSCI;
        float uyy = acc[5][0] * DSCI, vyy = acc[5][1] * DSCI;
        out[0 * NPTS + warp] = ut + (u * ux + v * uy) + px - NUF * (uxx + uyy);
        out[1 * NPTS + warp] = vt + (u * vx + v * vy) + py - NUF * (vxx + vyy);
        out[2 * NPTS + warp] = ux + vy;
    }
}

extern "C" void kernel_launch(void* const* d_in, const int* in_sizes, int n_in,
                              void* d_out, int out_size) {
    const float* t  = (const float*)d_in[0];
    const float* x  = (const float*)d_in[1];
    const float* y  = (const float*)d_in[2];
    const float* W0 = (const float*)d_in[3];
    const float* b0 = (const float*)d_in[4];
    const float* Wm[5] = {(const float*)d_in[5], (const float*)d_in[7], (const float*)d_in[9],
                          (const float*)d_in[11], (const float*)d_in[13]};
    const float* bm[5] = {(const float*)d_in[6], (const float*)d_in[8], (const float*)d_in[10],
                          (const float*)d_in[12], (const float*)d_in[14]};
    const float* W6 = (const float*)d_in[15];
    const float* b6 = (const float*)d_in[16];
    float* out = (float*)d_out;

    __half *sh, *sl, *wh, *wl;
    float* Z;
    cudaGetSymbolAddress((void**)&sh, g_sh);
    cudaGetSymbolAddress((void**)&sl, g_sl);
    cudaGetSymbolAddress((void**)&Z, g_Z);
    cudaGetSymbolAddress((void**)&wh, g_wh);
    cudaGetSymbolAddress((void**)&wl, g_wl);
    cudaFuncSetAttribute(k_gemm, cudaFuncAttributeMaxDynamicSharedMemorySize, SMEM_BYTES);

    k_wprep<<<dim3(256, 5), 256>>>(Wm[0], Wm[1], Wm[2], Wm[3], Wm[4], wh, wl);
    k_init<<<NPTS, 256>>>(t, x, y, W0, b0, sh, sl);
    for (int L = 0; L < 5; L++) {
        k_gemm<<<GRID_M, 256, SMEM_BYTES>>>(sh, sl, wh + (size_t)L * 65536,
                                            wl + (size_t)L * 65536, Z);
        k_act<<<(int)(NEL / 256), 256>>>(Z, bm[L], sh, sl);
    }
    k_final<<<NPTS / 8, 256>>>(sh, sl, W6, b6, out);
}

// round 5
// speedup vs baseline: 2.2779x; 1.2458x over previous
#include <cuda_runtime.h>
#include <cuda_fp16.h>
#include <cstdint>

#define NPTS 16384
#define HID  256
#define NUF  0.01f
static constexpr size_t NEL = (size_t)NPTS * HID;
static constexpr int MT = 96;                       // rows per CTA tile: 16 points x 6 channels
static constexpr int GRID_M = 6 * NPTS / MT;        // 1024
static constexpr float DSC  = 0.0625f;              // derivative-channel storage scale
static constexpr float DSCI = 16.0f;

// stage layout (bytes): A hi/lo 96x64 fp16, W hi/lo 256x64 fp16
static constexpr int ST_AH = 0;
static constexpr int ST_AL = 12288;
static constexpr int ST_WH = 24576;
static constexpr int ST_WL = 57344;
static constexpr int STAGE = 90112;
static constexpr int SMEM_BYTES = 2 * STAGE;        // 180224
static constexpr int ZS_LD = 264;                   // fp32 stride of epilogue staging tile

__device__ __align__(256) __half g_sh[6 * NEL];     // state hi (rho layout)
__device__ __align__(256) __half g_sl[6 * NEL];     // state lo
__device__ __align__(256) __half g_wh[5][65536];    // W^T hi [n][k]
__device__ __align__(256) __half g_wl[5][65536];    // W^T lo

__device__ __forceinline__ uint32_t smem_u32(const void* p) {
    uint32_t a;
    asm("{ .reg .u64 t; cvta.to.shared.u64 t, %1; cvt.u32.u64 %0, t; }" : "=r"(a) : "l"(p));
    return a;
}
__device__ __forceinline__ uint32_t swz(uint32_t o) { return o ^ ((o >> 3) & 0x70); }
__device__ __forceinline__ void cp16(uint32_t dst, const void* src) {
    asm volatile("cp.async.cg.shared.global [%0], [%1], 16;" :: "r"(dst), "l"(src) : "memory");
}
__device__ __forceinline__ void ldsm4(uint32_t* r, uint32_t addr) {
    asm volatile("ldmatrix.sync.aligned.m8n8.x4.shared.b16 {%0,%1,%2,%3}, [%4];"
                 : "=r"(r[0]), "=r"(r[1]), "=r"(r[2]), "=r"(r[3]) : "r"(addr));
}
__device__ __forceinline__ void mma16816(float* c, const uint32_t* a, uint32_t b0, uint32_t b1) {
    asm volatile("mma.sync.aligned.m16n8k16.row.col.f32.f16.f16.f32 "
                 "{%0,%1,%2,%3}, {%4,%5,%6,%7}, {%8,%9}, {%0,%1,%2,%3};"
                 : "+f"(c[0]), "+f"(c[1]), "+f"(c[2]), "+f"(c[3])
                 : "r"(a[0]), "r"(a[1]), "r"(a[2]), "r"(a[3]), "r"(b0), "r"(b1));
}
__device__ __forceinline__ void split16(float x, __half& h, __half& l) {
    h = __float2half_rn(x);
    l = __float2half_rn(x - __half2float(h));
}
// rho-layout row index for (point p, channel ch)
__device__ __forceinline__ size_t rho(int p, int ch) {
    return (size_t)(p >> 4) * 96 + ch * 16 + (p & 15);
}

// ---------- weight prep: W^T split into fp16 hi/lo ----------
__global__ void k_wprep(const float* W1, const float* W2, const float* W3,
                        const float* W4, const float* W5,
                        __half* __restrict__ wh, __half* __restrict__ wl) {
    int L = blockIdx.y, k = blockIdx.x, n = threadIdx.x;
    const float* W = (L == 0) ? W1 : (L == 1) ? W2 : (L == 2) ? W3 : (L == 3) ? W4 : W5;
    float w = W[k * 256 + n];
    __half h, l;
    split16(w, h, l);
    size_t o = (size_t)L * 65536 + (size_t)n * 256 + k;
    wh[o] = h;
    wl[o] = l;
}

// ---------- layer 0: inputs -> activated 6-channel state, rho layout ----------
__global__ void k_init(const float* __restrict__ t, const float* __restrict__ x,
                       const float* __restrict__ y, const float* __restrict__ W0,
                       const float* __restrict__ b0,
                       __half* __restrict__ oh, __half* __restrict__ ol) {
    int i = blockIdx.x, j = threadIdx.x;
    float w0 = W0[j], w1 = W0[256 + j], w2 = W0[512 + j];
    float a = t[i] * w0 + x[i] * w1 + y[i] * w2 + b0[j];
    float s, c;
    sincosf(a, &s, &c);
    float r[6] = {s, c * w0, c * w1, c * w2, -s * w1 * w1, -s * w2 * w2};
#pragma unroll
    for (int ch = 0; ch < 6; ch++) {
        float v = (ch == 0) ? r[ch] : r[ch] * DSC;
        __half h, l;
        split16(v, h, l);
        size_t o = rho(i, ch) * 256 + j;
        oh[o] = h;
        ol[o] = l;
    }
}

// ---------- fused fp16x3 GEMM + activation: state' = act(state @ W + b), in place ----------
__global__ void __launch_bounds__(256, 1)
k_gemm(__half* __restrict__ Sh, __half* __restrict__ Sl,
       const __half* __restrict__ Wh, const __half* __restrict__ Wl,
       const float* __restrict__ b) {
    extern __shared__ char smem[];
    const uint32_t sb = smem_u32(smem);
    const int tid = threadIdx.x, lane = tid & 31, wid = tid >> 5;
    const int mt = blockIdx.x;
    const int warpM = (wid >> 2) * 48, warpN = (wid & 3) * 64;

    const __half* arh = Sh + (size_t)mt * MT * 256;
    const __half* arl = Sl + (size_t)mt * MT * 256;

    auto issue = [&](int c, int buf) {
        uint32_t base = sb + buf * STAGE;
#pragma unroll
        for (int m = 0; m < 2; m++) {
            const __half* src = m ? arl : arh;
            uint32_t dstb = base + (m ? ST_AL : ST_AH);
#pragma unroll
            for (int i = 0; i < 3; i++) {             // 96 rows x 8 groups / 256 thr
                int idx = tid + i * 256, r = idx >> 3, q = idx & 7;
                cp16(dstb + swz(r * 128 + q * 16), src + (size_t)r * 256 + c * 64 + q * 8);
            }
        }
#pragma unroll
        for (int m = 0; m < 2; m++) {
            const __half* src = m ? Wl : Wh;
            uint32_t dstb = base + (m ? ST_WL : ST_WH);
#pragma unroll
            for (int i = 0; i < 8; i++) {             // 256 rows x 8 groups / 256 thr
                int idx = tid + i * 256, n = idx >> 3, q = idx & 7;
                cp16(dstb + swz(n * 128 + q * 16), src + (size_t)n * 256 + c * 64 + q * 8);
            }
        }
        asm volatile("cp.async.commit_group;" ::: "memory");
    };

    float acc[3][8][4];
#pragma unroll
    for (int mi = 0; mi < 3; mi++)
        for (int nj = 0; nj < 8; nj++)
            for (int q = 0; q < 4; q++) acc[mi][nj][q] = 0.f;

    issue(0, 0);
    issue(1, 1);

    const int lr = lane & 7, g = lane >> 3;
    const int roff = (g & 1) * 8 + lr;
    const int koff = (g >> 1) * 16;

    for (int c = 0; c < 4; c++) {
        const int buf = c & 1;
        if (c < 3) asm volatile("cp.async.wait_group 1;" ::: "memory");
        else       asm volatile("cp.async.wait_group 0;" ::: "memory");
        __syncthreads();
        const uint32_t base = sb + buf * STAGE;

#pragma unroll
        for (int ks = 0; ks < 4; ks++) {
            const int kb = ks * 32 + koff;
            uint32_t a_hi[3][4], a_lo[3][4], bq[4][4];
#pragma unroll
            for (int p = 0; p < 4; p++)
                ldsm4(bq[p], base + ST_WH + swz((warpN + p * 16 + roff) * 128 + kb));
#pragma unroll
            for (int mi = 0; mi < 3; mi++)
                ldsm4(a_hi[mi], base + ST_AH + swz((warpM + mi * 16 + roff) * 128 + kb));
#pragma unroll
            for (int mi = 0; mi < 3; mi++)
#pragma unroll
                for (int p = 0; p < 4; p++) {
                    mma16816(acc[mi][2 * p],     a_hi[mi], bq[p][0], bq[p][2]);
                    mma16816(acc[mi][2 * p + 1], a_hi[mi], bq[p][1], bq[p][3]);
                }
#pragma unroll
            for (int mi = 0; mi < 3; mi++)
                ldsm4(a_lo[mi], base + ST_AL + swz((warpM + mi * 16 + roff) * 128 + kb));
#pragma unroll
            for (int mi = 0; mi < 3; mi++)
#pragma unroll
                for (int p = 0; p < 4; p++) {
                    mma16816(acc[mi][2 * p],     a_lo[mi], bq[p][0], bq[p][2]);
                    mma16816(acc[mi][2 * p + 1], a_lo[mi], bq[p][1], bq[p][3]);
                }
#pragma unroll
            for (int p = 0; p < 4; p++)
                ldsm4(bq[p], base + ST_WL + swz((warpN + p * 16 + roff) * 128 + kb));
#pragma unroll
            for (int mi = 0; mi < 3; mi++)
#pragma unroll
                for (int p = 0; p < 4; p++) {
                    mma16816(acc[mi][2 * p],     a_hi[mi], bq[p][0], bq[p][2]);
                    mma16816(acc[mi][2 * p + 1], a_hi[mi], bq[p][1], bq[p][3]);
                }
        }
        __syncthreads();
        if (c + 2 < 4) issue(c + 2, buf);
    }

    // ---- fused epilogue: stage Z in smem, apply bias + sin chain rule, store state in place ----
    float* Zs = (float*)smem;                         // 96 x ZS_LD fp32 (101376 B < SMEM_BYTES)
    const int qr = lane >> 2, qc = (lane & 3) * 2;
#pragma unroll
    for (int mi = 0; mi < 3; mi++) {
        const int r0 = warpM + mi * 16 + qr;
#pragma unroll
        for (int nj = 0; nj < 8; nj++) {
            const int col = warpN + nj * 8 + qc;
            *(float2*)(Zs + (size_t)r0 * ZS_LD + col) = make_float2(acc[mi][nj][0], acc[mi][nj][1]);
            *(float2*)(Zs + (size_t)(r0 + 8) * ZS_LD + col) = make_float2(acc[mi][nj][2], acc[mi][nj][3]);
        }
    }
    __syncthreads();

    const int j = tid;
    const float bj = __ldg(b + j);
    const size_t g0 = (size_t)mt * MT;
#pragma unroll 4
    for (int pl = 0; pl < 16; pl++) {
        float a0 = Zs[(0 * 16 + pl) * ZS_LD + j] + bj;
        float a1 = Zs[(1 * 16 + pl) * ZS_LD + j] * DSCI;
        float a2 = Zs[(2 * 16 + pl) * ZS_LD + j] * DSCI;
        float a3 = Zs[(3 * 16 + pl) * ZS_LD + j] * DSCI;
        float a4 = Zs[(4 * 16 + pl) * ZS_LD + j] * DSCI;
        float a5 = Zs[(5 * 16 + pl) * ZS_LD + j] * DSCI;
        float s, c;
        sincosf(a0, &s, &c);
        float r[6] = {s, c * a1, c * a2, c * a3,
                      c * a4 - s * a2 * a2, c * a5 - s * a3 * a3};
#pragma unroll
        for (int ch = 0; ch < 6; ch++) {
            float v = (ch == 0) ? r[ch] : r[ch] * DSC;
            __half h, l;
            split16(v, h, l);
            size_t o = (g0 + ch * 16 + pl) * 256 + j;
            Sh[o] = h;
            Sl[o] = l;
        }
    }
}

// ---------- final layer (256->3) + NS residuals, rho layout ----------
__global__ void k_final(const __half* __restrict__ ih, const __half* __restrict__ il,
                        const float* __restrict__ W6, const float* __restrict__ b6,
                        float* __restrict__ out) {
    const int warp = (blockIdx.x * blockDim.x + threadIdx.x) >> 5;
    const int lane = threadIdx.x & 31;
    if (warp >= NPTS) return;
    float acc[6][3];
#pragma unroll
    for (int ch = 0; ch < 6; ch++)
        for (int o = 0; o < 3; o++) acc[ch][o] = 0.f;
    for (int k = lane; k < HID; k += 32) {
        float w0 = W6[k * 3], w1 = W6[k * 3 + 1], w2 = W6[k * 3 + 2];
#pragma unroll
        for (int ch = 0; ch < 6; ch++) {
            size_t o = rho(warp, ch) * 256 + k;
            float h = __half2float(ih[o]) + __half2float(il[o]);
            acc[ch][0] += h * w0; acc[ch][1] += h * w1; acc[ch][2] += h * w2;
        }
    }
#pragma unroll
    for (int ch = 0; ch < 6; ch++)
        for (int o = 0; o < 3; o++)
            for (int off = 16; off; off >>= 1)
                acc[ch][o] += __shfl_xor_sync(0xFFFFFFFFu, acc[ch][o], off);
    if (lane == 0) {
        float u = acc[0][0] + b6[0], v = acc[0][1] + b6[1];
        float ut = acc[1][0] * DSCI, vt = acc[1][1] * DSCI;
        float ux = acc[2][0] * DSCI, vx = acc[2][1] * DSCI, px = acc[2][2] * DSCI;
        float uy = acc[3][0] * DSCI, vy = acc[3][1] * DSCI, py = acc[3][2] * DSCI;
        float uxx = acc[4][0] * DSCI, vxx = acc[4][1] * DSCI;
        float uyy = acc[5][0] * DSCI, vyy = acc[5][1] * DSCI;
        out[0 * NPTS + warp] = ut + (u * ux + v * uy) + px - NUF * (uxx + uyy);
        out[1 * NPTS + warp] = vt + (u * vx + v * vy) + py - NUF * (vxx + vyy);
        out[2 * NPTS + warp] = ux + vy;
    }
}

extern "C" void kernel_launch(void* const* d_in, const int* in_sizes, int n_in,
                              void* d_out, int out_size) {
    const float* t  = (const float*)d_in[0];
    const float* x  = (const float*)d_in[1];
    const float* y  = (const float*)d_in[2];
    const float* W0 = (const float*)d_in[3];
    const float* b0 = (const float*)d_in[4];
    const float* Wm[5] = {(const float*)d_in[5], (const float*)d_in[7], (const float*)d_in[9],
                          (const float*)d_in[11], (const float*)d_in[13]};
    const float* bm[5] = {(const float*)d_in[6], (const float*)d_in[8], (const float*)d_in[10],
                          (const float*)d_in[12], (const float*)d_in[14]};
    const float* W6 = (const float*)d_in[15];
    const float* b6 = (const float*)d_in[16];
    float* out = (float*)d_out;

    __half *sh, *sl, *wh, *wl;
    cudaGetSymbolAddress((void**)&sh, g_sh);
    cudaGetSymbolAddress((void**)&sl, g_sl);
    cudaGetSymbolAddress((void**)&wh, g_wh);
    cudaGetSymbolAddress((void**)&wl, g_wl);
    cudaFuncSetAttribute(k_gemm, cudaFuncAttributeMaxDynamicSharedMemorySize, SMEM_BYTES);

    k_wprep<<<dim3(256, 5), 256>>>(Wm[0], Wm[1], Wm[2], Wm[3], Wm[4], wh, wl);
    k_init<<<NPTS, 256>>>(t, x, y, W0, b0, sh, sl);
    for (int L = 0; L < 5; L++) {
        k_gemm<<<GRID_M, 256, SMEM_BYTES>>>(sh, sl, wh + (size_t)L * 65536,
                                            wl + (size_t)L * 65536, bm[L]);
    }
    k_final<<<NPTS / 8, 256>>>(sh, sl, W6, b6, out);
}

// round 6
// speedup vs baseline: 2.3330x; 1.0242x over previous
#include <cuda_runtime.h>
#include <cuda_fp16.h>
#include <cstdint>

#define NPTS 16384
#define HID  256
#define NUF  0.01f
static constexpr size_t NEL = (size_t)NPTS * HID;
static constexpr int MT = 96;                       // rows per CTA tile: 16 points x 6 channels
static constexpr int GRID_M = 6 * NPTS / MT;        // 1024
static constexpr int NTHR = 384;                    // 12 warps, 3 per SMSP
static constexpr float DSC  = 0.0625f;
static constexpr float DSCI = 16.0f;

// stage layout (bytes): A hi/lo 96x64 fp16, W hi/lo 256x64 fp16
static constexpr int ST_AH = 0;
static constexpr int ST_AL = 12288;
static constexpr int ST_WH = 24576;
static constexpr int ST_WL = 57344;
static constexpr int STAGE = 90112;
static constexpr int SMEM_BYTES = 2 * STAGE;        // 180224
static constexpr int ZS_LD = 264;                   // fp32 stride of epilogue staging tile

__device__ __align__(256) __half g_sh[6 * NEL];     // state hi (rho layout)
__device__ __align__(256) __half g_sl[6 * NEL];     // state lo
__device__ __align__(256) __half g_wh[5][65536];    // W^T hi [n][k]
__device__ __align__(256) __half g_wl[5][65536];    // W^T lo

__device__ __forceinline__ uint32_t smem_u32(const void* p) {
    uint32_t a;
    asm("{ .reg .u64 t; cvta.to.shared.u64 t, %1; cvt.u32.u64 %0, t; }" : "=r"(a) : "l"(p));
    return a;
}
__device__ __forceinline__ uint32_t swz(uint32_t o) { return o ^ ((o >> 3) & 0x70); }
__device__ __forceinline__ void cp16(uint32_t dst, const void* src) {
    asm volatile("cp.async.cg.shared.global [%0], [%1], 16;" :: "r"(dst), "l"(src) : "memory");
}
__device__ __forceinline__ void ldsm4(uint32_t* r, uint32_t addr) {
    asm volatile("ldmatrix.sync.aligned.m8n8.x4.shared.b16 {%0,%1,%2,%3}, [%4];"
                 : "=r"(r[0]), "=r"(r[1]), "=r"(r[2]), "=r"(r[3]) : "r"(addr));
}
__device__ __forceinline__ void mma16816(float* c, const uint32_t* a, uint32_t b0, uint32_t b1) {
    asm volatile("mma.sync.aligned.m16n8k16.row.col.f32.f16.f16.f32 "
                 "{%0,%1,%2,%3}, {%4,%5,%6,%7}, {%8,%9}, {%0,%1,%2,%3};"
                 : "+f"(c[0]), "+f"(c[1]), "+f"(c[2]), "+f"(c[3])
                 : "r"(a[0]), "r"(a[1]), "r"(a[2]), "r"(a[3]), "r"(b0), "r"(b1));
}
__device__ __forceinline__ void split16(float x, __half& h, __half& l) {
    h = __float2half_rn(x);
    l = __float2half_rn(x - __half2float(h));
}
__device__ __forceinline__ size_t rho(int p, int ch) {
    return (size_t)(p >> 4) * 96 + ch * 16 + (p & 15);
}

// ---------- weight prep ----------
__global__ void k_wprep(const float* W1, const float* W2, const float* W3,
                        const float* W4, const float* W5,
                        __half* __restrict__ wh, __half* __restrict__ wl) {
    int L = blockIdx.y, k = blockIdx.x, n = threadIdx.x;
    const float* W = (L == 0) ? W1 : (L == 1) ? W2 : (L == 2) ? W3 : (L == 3) ? W4 : W5;
    float w = W[k * 256 + n];
    __half h, l;
    split16(w, h, l);
    size_t o = (size_t)L * 65536 + (size_t)n * 256 + k;
    wh[o] = h;
    wl[o] = l;
}

// ---------- layer 0 ----------
__global__ void k_init(const float* __restrict__ t, const float* __restrict__ x,
                       const float* __restrict__ y, const float* __restrict__ W0,
                       const float* __restrict__ b0,
                       __half* __restrict__ oh, __half* __restrict__ ol) {
    int i = blockIdx.x, j = threadIdx.x;
    float w0 = W0[j], w1 = W0[256 + j], w2 = W0[512 + j];
    float a = t[i] * w0 + x[i] * w1 + y[i] * w2 + b0[j];
    float s, c;
    sincosf(a, &s, &c);
    float r[6] = {s, c * w0, c * w1, c * w2, -s * w1 * w1, -s * w2 * w2};
#pragma unroll
    for (int ch = 0; ch < 6; ch++) {
        float v = (ch == 0) ? r[ch] : r[ch] * DSC;
        __half h, l;
        split16(v, h, l);
        size_t o = rho(i, ch) * 256 + j;
        oh[o] = h;
        ol[o] = l;
    }
}

// ---------- fused fp16x3 GEMM + activation, in place, 12 warps ----------
__global__ void __launch_bounds__(NTHR, 1)
k_gemm(__half* __restrict__ Sh, __half* __restrict__ Sl,
       const __half* __restrict__ Wh, const __half* __restrict__ Wl,
       const float* __restrict__ b) {
    extern __shared__ char smem[];
    const uint32_t sb = smem_u32(smem);
    const int tid = threadIdx.x, lane = tid & 31, wid = tid >> 5;
    const int mt = blockIdx.x;
    const int warpM = (wid >> 2) * 32, warpN = (wid & 3) * 64;  // 3x4 warp grid, 32x64 tiles

    const __half* arh = Sh + (size_t)mt * MT * 256;
    const __half* arl = Sl + (size_t)mt * MT * 256;

    auto issue = [&](int c, int buf) {
        uint32_t base = sb + buf * STAGE;
        // A hi/lo: 96 rows x 8 16B-groups = 768 per matrix; 2 iters x 384 thr
#pragma unroll
        for (int m = 0; m < 2; m++) {
            const __half* src = m ? arl : arh;
            uint32_t dstb = base + (m ? ST_AL : ST_AH);
#pragma unroll
            for (int i = 0; i < 2; i++) {
                int idx = tid + i * NTHR, r = idx >> 3, q = idx & 7;
                cp16(dstb + swz(r * 128 + q * 16), src + (size_t)r * 256 + c * 64 + q * 8);
            }
        }
        // W hi/lo: 256 rows x 8 groups = 2048 per matrix; 6 iters x 384 with guard
#pragma unroll
        for (int m = 0; m < 2; m++) {
            const __half* src = m ? Wl : Wh;
            uint32_t dstb = base + (m ? ST_WL : ST_WH);
#pragma unroll
            for (int i = 0; i < 6; i++) {
                int idx = tid + i * NTHR;
                if (idx < 2048) {
                    int n = idx >> 3, q = idx & 7;
                    cp16(dstb + swz(n * 128 + q * 16), src + (size_t)n * 256 + c * 64 + q * 8);
                }
            }
        }
        asm volatile("cp.async.commit_group;" ::: "memory");
    };

    float acc[2][8][4];
#pragma unroll
    for (int mi = 0; mi < 2; mi++)
        for (int nj = 0; nj < 8; nj++)
            for (int q = 0; q < 4; q++) acc[mi][nj][q] = 0.f;

    issue(0, 0);
    issue(1, 1);

    const int lr = lane & 7, g = lane >> 3;
    const int roff = (g & 1) * 8 + lr;
    const int koff = (g >> 1) * 16;

    for (int c = 0; c < 4; c++) {
        const int buf = c & 1;
        if (c < 3) asm volatile("cp.async.wait_group 1;" ::: "memory");
        else       asm volatile("cp.async.wait_group 0;" ::: "memory");
        __syncthreads();
        const uint32_t base = sb + buf * STAGE;

#pragma unroll
        for (int ks = 0; ks < 4; ks++) {
            const int kb = ks * 32 + koff;
            uint32_t a_hi[2][4], a_lo[2][4], bq[4][4];
#pragma unroll
            for (int p = 0; p < 4; p++)
                ldsm4(bq[p], base + ST_WH + swz((warpN + p * 16 + roff) * 128 + kb));
#pragma unroll
            for (int mi = 0; mi < 2; mi++)
                ldsm4(a_hi[mi], base + ST_AH + swz((warpM + mi * 16 + roff) * 128 + kb));
#pragma unroll
            for (int mi = 0; mi < 2; mi++)
                ldsm4(a_lo[mi], base + ST_AL + swz((warpM + mi * 16 + roff) * 128 + kb));
#pragma unroll
            for (int mi = 0; mi < 2; mi++)
#pragma unroll
                for (int p = 0; p < 4; p++) {
                    mma16816(acc[mi][2 * p],     a_hi[mi], bq[p][0], bq[p][2]);
                    mma16816(acc[mi][2 * p + 1], a_hi[mi], bq[p][1], bq[p][3]);
                }
#pragma unroll
            for (int mi = 0; mi < 2; mi++)
#pragma unroll
                for (int p = 0; p < 4; p++) {
                    mma16816(acc[mi][2 * p],     a_lo[mi], bq[p][0], bq[p][2]);
                    mma16816(acc[mi][2 * p + 1], a_lo[mi], bq[p][1], bq[p][3]);
                }
#pragma unroll
            for (int p = 0; p < 4; p++)
                ldsm4(bq[p], base + ST_WL + swz((warpN + p * 16 + roff) * 128 + kb));
#pragma unroll
            for (int mi = 0; mi < 2; mi++)
#pragma unroll
                for (int p = 0; p < 4; p++) {
                    mma16816(acc[mi][2 * p],     a_hi[mi], bq[p][0], bq[p][2]);
                    mma16816(acc[mi][2 * p + 1], a_hi[mi], bq[p][1], bq[p][3]);
                }
        }
        __syncthreads();
        if (c + 2 < 4) issue(c + 2, buf);
    }

    // ---- fused epilogue ----
    float* Zs = (float*)smem;                         // 96 x ZS_LD fp32
    const int qr = lane >> 2, qc = (lane & 3) * 2;
#pragma unroll
    for (int mi = 0; mi < 2; mi++) {
        const int r0 = warpM + mi * 16 + qr;
#pragma unroll
        for (int nj = 0; nj < 8; nj++) {
            const int col = warpN + nj * 8 + qc;
            *(float2*)(Zs + (size_t)r0 * ZS_LD + col) = make_float2(acc[mi][nj][0], acc[mi][nj][1]);
            *(float2*)(Zs + (size_t)(r0 + 8) * ZS_LD + col) = make_float2(acc[mi][nj][2], acc[mi][nj][3]);
        }
    }
    __syncthreads();

    const size_t g0 = (size_t)mt * MT;
#pragma unroll
    for (int it = 0; it < 11; it++) {
        int task = tid + it * NTHR;                   // 16 points x 256 cols = 4096 tasks
        if (task >= 4096) break;
        int pl = task >> 8, j = task & 255;
        float bj = __ldg(b + j);
        float a0 = Zs[(0 * 16 + pl) * ZS_LD + j] + bj;
        float a1 = Zs[(1 * 16 + pl) * ZS_LD + j] * DSCI;
        float a2 = Zs[(2 * 16 + pl) * ZS_LD + j] * DSCI;
        float a3 = Zs[(3 * 16 + pl) * ZS_LD + j] * DSCI;
        float a4 = Zs[(4 * 16 + pl) * ZS_LD + j] * DSCI;
        float a5 = Zs[(5 * 16 + pl) * ZS_LD + j] * DSCI;
        float s, c;
        sincosf(a0, &s, &c);
        float r[6] = {s, c * a1, c * a2, c * a3,
                      c * a4 - s * a2 * a2, c * a5 - s * a3 * a3};
#pragma unroll
        for (int ch = 0; ch < 6; ch++) {
            float v = (ch == 0) ? r[ch] : r[ch] * DSC;
            __half h, l;
            split16(v, h, l);
            size_t o = (g0 + ch * 16 + pl) * 256 + j;
            Sh[o] = h;
            Sl[o] = l;
        }
    }
}

// ---------- final layer + NS residuals ----------
__global__ void k_final(const __half* __restrict__ ih, const __half* __restrict__ il,
                        const float* __restrict__ W6, const float* __restrict__ b6,
                        float* __restrict__ out) {
    const int warp = (blockIdx.x * blockDim.x + threadIdx.x) >> 5;
    const int lane = threadIdx.x & 31;
    if (warp >= NPTS) return;
    float acc[6][3];
#pragma unroll
    for (int ch = 0; ch < 6; ch++)
        for (int o = 0; o < 3; o++) acc[ch][o] = 0.f;
    for (int k = lane; k < HID; k += 32) {
        float w0 = W6[k * 3], w1 = W6[k * 3 + 1], w2 = W6[k * 3 + 2];
#pragma unroll
        for (int ch = 0; ch < 6; ch++) {
            size_t o = rho(warp, ch) * 256 + k;
            float h = __half2float(ih[o]) + __half2float(il[o]);
            acc[ch][0] += h * w0; acc[ch][1] += h * w1; acc[ch][2] += h * w2;
        }
    }
#pragma unroll
    for (int ch = 0; ch < 6; ch++)
        for (int o = 0; o < 3; o++)
            for (int off = 16; off; off >>= 1)
                acc[ch][o] += __shfl_xor_sync(0xFFFFFFFFu, acc[ch][o], off);
    if (lane == 0) {
        float u = acc[0][0] + b6[0], v = acc[0][1] + b6[1];
        float ut = acc[1][0] * DSCI, vt = acc[1][1] * DSCI;
        float ux = acc[2][0] * DSCI, vx = acc[2][1] * DSCI, px = acc[2][2] * DSCI;
        float uy = acc[3][0] * DSCI, vy = acc[3][1] * DSCI, py = acc[3][2] * DSCI;
        float uxx = acc[4][0] * DSCI, vxx = acc[4][1] * DSCI;
        float uyy = acc[5][0] * DSCI, vyy = acc[5][1] * DSCI;
        out[0 * NPTS + warp] = ut + (u * ux + v * uy) + px - NUF * (uxx + uyy);
        out[1 * NPTS + warp] = vt + (u * vx + v * vy) + py - NUF * (vxx + vyy);
        out[2 * NPTS + warp] = ux + vy;
    }
}

extern "C" void kernel_launch(void* const* d_in, const int* in_sizes, int n_in,
                              void* d_out, int out_size) {
    const float* t  = (const float*)d_in[0];
    const float* x  = (const float*)d_in[1];
    const float* y  = (const float*)d_in[2];
    const float* W0 = (const float*)d_in[3];
    const float* b0 = (const float*)d_in[4];
    const float* Wm[5] = {(const float*)d_in[5], (const float*)d_in[7], (const float*)d_in[9],
                          (const float*)d_in[11], (const float*)d_in[13]};
    const float* bm[5] = {(const float*)d_in[6], (const float*)d_in[8], (const float*)d_in[10],
                          (const float*)d_in[12], (const float*)d_in[14]};
    const float* W6 = (const float*)d_in[15];
    const float* b6 = (const float*)d_in[16];
    float* out = (float*)d_out;

    __half *sh, *sl, *wh, *wl;
    cudaGetSymbolAddress((void**)&sh, g_sh);
    cudaGetSymbolAddress((void**)&sl, g_sl);
    cudaGetSymbolAddress((void**)&wh, g_wh);
    cudaGetSymbolAddress((void**)&wl, g_wl);
    cudaFuncSetAttribute(k_gemm, cudaFuncAttributeMaxDynamicSharedMemorySize, SMEM_BYTES);

    k_wprep<<<dim3(256, 5), 256>>>(Wm[0], Wm[1], Wm[2], Wm[3], Wm[4], wh, wl);
    k_init<<<NPTS, 256>>>(t, x, y, W0, b0, sh, sl);
    for (int L = 0; L < 5; L++) {
        k_gemm<<<GRID_M, NTHR, SMEM_BYTES>>>(sh, sl, wh + (size_t)L * 65536,
                                             wl + (size_t)L * 65536, bm[L]);
    }
    k_final<<<NPTS / 8, 256>>>(sh, sl, W6, b6, out);
}

// round 8
// speedup vs baseline: 2.3383x; 1.0023x over previous
#include <cuda_runtime.h>
#include <cuda_fp16.h>
#include <cstdint>

#define NPTS 16384
#define HID  256
#define NUF  0.01f
static constexpr size_t NEL = (size_t)NPTS * HID;
static constexpr int MT = 96;                       // rows per CTA tile: 16 points x 6 channels
static constexpr int GRID_M = 6 * NPTS / MT;        // 1024
static constexpr int NTHR = 256;                    // 8 warps
static constexpr float DSC  = 0.0625f;
static constexpr float DSCI = 16.0f;

// stage layout (bytes): A hi/lo 96x64 fp16, W hi/lo 256x64 fp16
static constexpr int ST_AH = 0;
static constexpr int ST_AL = 12288;
static constexpr int ST_WH = 24576;
static constexpr int ST_WL = 57344;
static constexpr int STAGE = 90112;
static constexpr int SMEM_BYTES = 2 * STAGE;        // 180224
static constexpr int ZS_LD = 264;                   // fp32 stride of epilogue staging tile

__device__ __align__(256) __half g_sh[6 * NEL];     // state hi (rho layout)
__device__ __align__(256) __half g_sl[6 * NEL];     // state lo
__device__ __align__(256) __half g_wh[5][65536];    // W^T hi [n][k]
__device__ __align__(256) __half g_wl[5][65536];    // W^T lo

__device__ __forceinline__ uint32_t smem_u32(const void* p) {
    uint32_t a;
    asm("{ .reg .u64 t; cvta.to.shared.u64 t, %1; cvt.u32.u64 %0, t; }" : "=r"(a) : "l"(p));
    return a;
}
__device__ __forceinline__ uint32_t swz(uint32_t o) { return o ^ ((o >> 3) & 0x70); }
__device__ __forceinline__ void cp16(uint32_t dst, const void* src) {
    asm volatile("cp.async.cg.shared.global [%0], [%1], 16;" :: "r"(dst), "l"(src) : "memory");
}
__device__ __forceinline__ void ldsm4(uint32_t* r, uint32_t addr) {
    asm volatile("ldmatrix.sync.aligned.m8n8.x4.shared.b16 {%0,%1,%2,%3}, [%4];"
                 : "=r"(r[0]), "=r"(r[1]), "=r"(r[2]), "=r"(r[3]) : "r"(addr));
}
// fp32-accumulate MMA (main pass)
__device__ __forceinline__ void mma16816(float* c, const uint32_t* a, uint32_t b0, uint32_t b1) {
    asm volatile("mma.sync.aligned.m16n8k16.row.col.f32.f16.f16.f32 "
                 "{%0,%1,%2,%3}, {%4,%5,%6,%7}, {%8,%9}, {%0,%1,%2,%3};"
                 : "+f"(c[0]), "+f"(c[1]), "+f"(c[2]), "+f"(c[3])
                 : "r"(a[0]), "r"(a[1]), "r"(a[2]), "r"(a[3]), "r"(b0), "r"(b1));
}
// fp16-accumulate MMA (correction passes)
__device__ __forceinline__ void mma16816h(uint32_t* c, const uint32_t* a, uint32_t b0, uint32_t b1) {
    asm volatile("mma.sync.aligned.m16n8k16.row.col.f16.f16.f16.f16 "
                 "{%0,%1}, {%2,%3,%4,%5}, {%6,%7}, {%0,%1};"
                 : "+r"(c[0]), "+r"(c[1])
                 : "r"(a[0]), "r"(a[1]), "r"(a[2]), "r"(a[3]), "r"(b0), "r"(b1));
}
__device__ __forceinline__ void split16(float x, __half& h, __half& l) {
    h = __float2half_rn(x);
    l = __float2half_rn(x - __half2float(h));
}
__device__ __forceinline__ size_t rho(int p, int ch) {
    return (size_t)(p >> 4) * 96 + ch * 16 + (p & 15);
}

// ---------- weight prep ----------
__global__ void k_wprep(const float* W1, const float* W2, const float* W3,
                        const float* W4, const float* W5,
                        __half* __restrict__ wh, __half* __restrict__ wl) {
    int L = blockIdx.y, k = blockIdx.x, n = threadIdx.x;
    const float* W = (L == 0) ? W1 : (L == 1) ? W2 : (L == 2) ? W3 : (L == 3) ? W4 : W5;
    float w = W[k * 256 + n];
    __half h, l;
    split16(w, h, l);
    size_t o = (size_t)L * 65536 + (size_t)n * 256 + k;
    wh[o] = h;
    wl[o] = l;
}

// ---------- layer 0 ----------
__global__ void k_init(const float* __restrict__ t, const float* __restrict__ x,
                       const float* __restrict__ y, const float* __restrict__ W0,
                       const float* __restrict__ b0,
                       __half* __restrict__ oh, __half* __restrict__ ol) {
    int i = blockIdx.x, j = threadIdx.x;
    float w0 = W0[j], w1 = W0[256 + j], w2 = W0[512 + j];
    float a = t[i] * w0 + x[i] * w1 + y[i] * w2 + b0[j];
    float s, c;
    sincosf(a, &s, &c);
    float r[6] = {s, c * w0, c * w1, c * w2, -s * w1 * w1, -s * w2 * w2};
#pragma unroll
    for (int ch = 0; ch < 6; ch++) {
        float v = (ch == 0) ? r[ch] : r[ch] * DSC;
        __half h, l;
        split16(v, h, l);
        size_t o = rho(i, ch) * 256 + j;
        oh[o] = h;
        ol[o] = l;
    }
}

// ---------- fused fp16x3 GEMM (f32 main / f16 corrections) + activation, in place ----------
__global__ void __launch_bounds__(NTHR, 1)
k_gemm(__half* __restrict__ Sh, __half* __restrict__ Sl,
       const __half* __restrict__ Wh, const __half* __restrict__ Wl,
       const float* __restrict__ b) {
    extern __shared__ char smem[];
    const uint32_t sb = smem_u32(smem);
    const int tid = threadIdx.x, lane = tid & 31, wid = tid >> 5;
    const int mt = blockIdx.x;
    const int warpM = (wid >> 2) * 48, warpN = (wid & 3) * 64;  // 2x4 warps, 48x64 tiles

    const __half* arh = Sh + (size_t)mt * MT * 256;
    const __half* arl = Sl + (size_t)mt * MT * 256;

    auto issue = [&](int c, int buf) {
        uint32_t base = sb + buf * STAGE;
#pragma unroll
        for (int m = 0; m < 2; m++) {
            const __half* src = m ? arl : arh;
            uint32_t dstb = base + (m ? ST_AL : ST_AH);
#pragma unroll
            for (int i = 0; i < 3; i++) {
                int idx = tid + i * NTHR, r = idx >> 3, q = idx & 7;
                cp16(dstb + swz(r * 128 + q * 16), src + (size_t)r * 256 + c * 64 + q * 8);
            }
        }
#pragma unroll
        for (int m = 0; m < 2; m++) {
            const __half* src = m ? Wl : Wh;
            uint32_t dstb = base + (m ? ST_WL : ST_WH);
#pragma unroll
            for (int i = 0; i < 8; i++) {
                int idx = tid + i * NTHR, n = idx >> 3, q = idx & 7;
                cp16(dstb + swz(n * 128 + q * 16), src + (size_t)n * 256 + c * 64 + q * 8);
            }
        }
        asm volatile("cp.async.commit_group;" ::: "memory");
    };

    float acc[3][8][4];          // main hi*hi, fp32
    uint32_t accc[3][8][2];      // corrections, f16x2
#pragma unroll
    for (int mi = 0; mi < 3; mi++)
        for (int nj = 0; nj < 8; nj++) {
            for (int q = 0; q < 4; q++) acc[mi][nj][q] = 0.f;
            accc[mi][nj][0] = 0u; accc[mi][nj][1] = 0u;
        }

    issue(0, 0);
    issue(1, 1);

    const int lr = lane & 7, g = lane >> 3;
    const int roff = (g & 1) * 8 + lr;
    const int koff = (g >> 1) * 16;

    for (int c = 0; c < 4; c++) {
        const int buf = c & 1;
        if (c < 3) asm volatile("cp.async.wait_group 1;" ::: "memory");
        else       asm volatile("cp.async.wait_group 0;" ::: "memory");
        __syncthreads();
        const uint32_t base = sb + buf * STAGE;

#pragma unroll
        for (int ks = 0; ks < 4; ks++) {
            const int kb = ks * 32 + koff;
            uint32_t a_hi[3][4], a_lo[3][4], bq[4][4];
#pragma unroll
            for (int p = 0; p < 4; p++)
                ldsm4(bq[p], base + ST_WH + swz((warpN + p * 16 + roff) * 128 + kb));
#pragma unroll
            for (int mi = 0; mi < 3; mi++)
                ldsm4(a_hi[mi], base + ST_AH + swz((warpM + mi * 16 + roff) * 128 + kb));
            // main: hi*hi -> fp32 acc
#pragma unroll
            for (int mi = 0; mi < 3; mi++)
#pragma unroll
                for (int p = 0; p < 4; p++) {
                    mma16816(acc[mi][2 * p],     a_hi[mi], bq[p][0], bq[p][2]);
                    mma16816(acc[mi][2 * p + 1], a_hi[mi], bq[p][1], bq[p][3]);
                }
            // correction: lo*hi -> f16 acc
#pragma unroll
            for (int mi = 0; mi < 3; mi++)
                ldsm4(a_lo[mi], base + ST_AL + swz((warpM + mi * 16 + roff) * 128 + kb));
#pragma unroll
            for (int mi = 0; mi < 3; mi++)
#pragma unroll
                for (int p = 0; p < 4; p++) {
                    mma16816h(accc[mi][2 * p],     a_lo[mi], bq[p][0], bq[p][2]);
                    mma16816h(accc[mi][2 * p + 1], a_lo[mi], bq[p][1], bq[p][3]);
                }
            // correction: hi*lo -> f16 acc
#pragma unroll
            for (int p = 0; p < 4; p++)
                ldsm4(bq[p], base + ST_WL + swz((warpN + p * 16 + roff) * 128 + kb));
#pragma unroll
            for (int mi = 0; mi < 3; mi++)
#pragma unroll
                for (int p = 0; p < 4; p++) {
                    mma16816h(accc[mi][2 * p],     a_hi[mi], bq[p][0], bq[p][2]);
                    mma16816h(accc[mi][2 * p + 1], a_hi[mi], bq[p][1], bq[p][3]);
                }
        }
        __syncthreads();
        if (c + 2 < 4) issue(c + 2, buf);
    }

    // ---- fused epilogue: combine f32 main + f16 corrections, stage, activate ----
    float* Zs = (float*)smem;                         // 96 x ZS_LD fp32
    const int qr = lane >> 2, qc = (lane & 3) * 2;
#pragma unroll
    for (int mi = 0; mi < 3; mi++) {
        const int r0 = warpM + mi * 16 + qr;
#pragma unroll
        for (int nj = 0; nj < 8; nj++) {
            const int col = warpN + nj * 8 + qc;
            float2 c0 = __half22float2(*(__half2*)&accc[mi][nj][0]);
            float2 c1 = __half22float2(*(__half2*)&accc[mi][nj][1]);
            *(float2*)(Zs + (size_t)r0 * ZS_LD + col) =
                make_float2(acc[mi][nj][0] + c0.x, acc[mi][nj][1] + c0.y);
            *(float2*)(Zs + (size_t)(r0 + 8) * ZS_LD + col) =
                make_float2(acc[mi][nj][2] + c1.x, acc[mi][nj][3] + c1.y);
        }
    }
    __syncthreads();

    const int j = tid;
    const float bj = __ldg(b + j);
    const size_t g0 = (size_t)mt * MT;
#pragma unroll 4
    for (int pl = 0; pl < 16; pl++) {
        float a0 = Zs[(0 * 16 + pl) * ZS_LD + j] + bj;
        float a1 = Zs[(1 * 16 + pl) * ZS_LD + j] * DSCI;
        float a2 = Zs[(2 * 16 + pl) * ZS_LD + j] * DSCI;
        float a3 = Zs[(3 * 16 + pl) * ZS_LD + j] * DSCI;
        float a4 = Zs[(4 * 16 + pl) * ZS_LD + j] * DSCI;
        float a5 = Zs[(5 * 16 + pl) * ZS_LD + j] * DSCI;
        float s, c;
        sincosf(a0, &s, &c);
        float r[6] = {s, c * a1, c * a2, c * a3,
                      c * a4 - s * a2 * a2, c * a5 - s * a3 * a3};
#pragma unroll
        for (int ch = 0; ch < 6; ch++) {
            float v = (ch == 0) ? r[ch] : r[ch] * DSC;
            __half h, l;
            split16(v, h, l);
            size_t o = (g0 + ch * 16 + pl) * 256 + j;
            Sh[o] = h;
            Sl[o] = l;
        }
    }
}

// ---------- final layer + NS residuals ----------
__global__ void k_final(const __half* __restrict__ ih, const __half* __restrict__ il,
                        const float* __restrict__ W6, const float* __restrict__ b6,
                        float* __restrict__ out) {
    const int warp = (blockIdx.x * blockDim.x + threadIdx.x) >> 5;
    const int lane = threadIdx.x & 31;
    if (warp >= NPTS) return;
    float acc[6][3];
#pragma unroll
    for (int ch = 0; ch < 6; ch++)
        for (int o = 0; o < 3; o++) acc[ch][o] = 0.f;
    for (int k = lane; k < HID; k += 32) {
        float w0 = W6[k * 3], w1 = W6[k * 3 + 1], w2 = W6[k * 3 + 2];
#pragma unroll
        for (int ch = 0; ch < 6; ch++) {
            size_t o = rho(warp, ch) * 256 + k;
            float h = __half2float(ih[o]) + __half2float(il[o]);
            acc[ch][0] += h * w0; acc[ch][1] += h * w1; acc[ch][2] += h * w2;
        }
    }
#pragma unroll
    for (int ch = 0; ch < 6; ch++)
        for (int o = 0; o < 3; o++)
            for (int off = 16; off; off >>= 1)
                acc[ch][o] += __shfl_xor_sync(0xFFFFFFFFu, acc[ch][o], off);
    if (lane == 0) {
        float u = acc[0][0] + b6[0], v = acc[0][1] + b6[1];
        float ut = acc[1][0] * DSCI, vt = acc[1][1] * DSCI;
        float ux = acc[2][0] * DSCI, vx = acc[2][1] * DSCI, px = acc[2][2] * DSCI;
        float uy = acc[3][0] * DSCI, vy = acc[3][1] * DSCI, py = acc[3][2] * DSCI;
        float uxx = acc[4][0] * DSCI, vxx = acc[4][1] * DSCI;
        float uyy = acc[5][0] * DSCI, vyy = acc[5][1] * DSCI;
        out[0 * NPTS + warp] = ut + (u * ux + v * uy) + px - NUF * (uxx + uyy);
        out[1 * NPTS + warp] = vt + (u * vx + v * vy) + py - NUF * (vxx + vyy);
        out[2 * NPTS + warp] = ux + vy;
    }
}

extern "C" void kernel_launch(void* const* d_in, const int* in_sizes, int n_in,
                              void* d_out, int out_size) {
    const float* t  = (const float*)d_in[0];
    const float* x  = (const float*)d_in[1];
    const float* y  = (const float*)d_in[2];
    const float* W0 = (const float*)d_in[3];
    const float* b0 = (const float*)d_in[4];
    const float* Wm[5] = {(const float*)d_in[5], (const float*)d_in[7], (const float*)d_in[9],
                          (const float*)d_in[11], (const float*)d_in[13]};
    const float* bm[5] = {(const float*)d_in[6], (const float*)d_in[8], (const float*)d_in[10],
                          (const float*)d_in[12], (const float*)d_in[14]};
    const float* W6 = (const float*)d_in[15];
    const float* b6 = (const float*)d_in[16];
    float* out = (float*)d_out;

    __half *sh, *sl, *wh, *wl;
    cudaGetSymbolAddress((void**)&sh, g_sh);
    cudaGetSymbolAddress((void**)&sl, g_sl);
    cudaGetSymbolAddress((void**)&wh, g_wh);
    cudaGetSymbolAddress((void**)&wl, g_wl);
    cudaFuncSetAttribute(k_gemm, cudaFuncAttributeMaxDynamicSharedMemorySize, SMEM_BYTES);

    k_wprep<<<dim3(256, 5), 256>>>(Wm[0], Wm[1], Wm[2], Wm[3], Wm[4], wh, wl);
    k_init<<<NPTS, 256>>>(t, x, y, W0, b0, sh, sl);
    for (int L = 0; L < 5; L++) {
        k_gemm<<<GRID_M, NTHR, SMEM_BYTES>>>(sh, sl, wh + (size_t)L * 65536,
                                             wl + (size_t)L * 65536, bm[L]);
    }
    k_final<<<NPTS / 8, 256>>>(sh, sl, W6, b6, out);
}

// round 14
// speedup vs baseline: 2.3756x; 1.0159x over previous
#include <cuda_runtime.h>
#include <cuda_fp16.h>
#include <cstdint>

#define NPTS 16384
#define HID  256
#define NUF  0.01f
static constexpr size_t NEL = (size_t)NPTS * HID;
static constexpr int NCH = 5;                       // h, h_t, h_x, h_y, h_L (Laplacian)
static constexpr int MT = 80;                       // 16 points x 5 channels
static constexpr int GRID_M = NCH * NPTS / MT;      // 1024
static constexpr int NTHR = 256;
static constexpr float DSC  = 0.0625f;
static constexpr float DSCI = 16.0f;

// stage layout (bytes): A hi/lo 80x64 f16, W hi/lo 256x64 f16
static constexpr int ST_AH = 0;
static constexpr int ST_AL = 10240;
static constexpr int ST_WH = 20480;
static constexpr int ST_WL = 53248;
static constexpr int STAGE = 86016;
static constexpr int SMEM_BYTES = 2 * STAGE;        // 172032
static constexpr int ZS_LD = 264;                   // fp32 stride of epilogue staging (80 x 264)

__device__ __align__(256) __half g_sh[NCH * NEL];   // state hi (rho layout)
__device__ __align__(256) __half g_sl[NCH * NEL];   // state lo
__device__ __align__(256) __half g_wh[5][65536];    // W^T hi [n][k]
__device__ __align__(256) __half g_wl[5][65536];    // W^T lo

__device__ __forceinline__ uint32_t smem_u32(const void* p) {
    uint32_t a;
    asm("{ .reg .u64 t; cvta.to.shared.u64 t, %1; cvt.u32.u64 %0, t; }" : "=r"(a) : "l"(p));
    return a;
}
__device__ __forceinline__ uint32_t swz(uint32_t o) { return o ^ ((o >> 3) & 0x70); }
__device__ __forceinline__ void cp16(uint32_t dst, const void* src) {
    asm volatile("cp.async.cg.shared.global [%0], [%1], 16;" :: "r"(dst), "l"(src) : "memory");
}
__device__ __forceinline__ void ldsm4(uint32_t* r, uint32_t addr) {
    asm volatile("ldmatrix.sync.aligned.m8n8.x4.shared.b16 {%0,%1,%2,%3}, [%4];"
                 : "=r"(r[0]), "=r"(r[1]), "=r"(r[2]), "=r"(r[3]) : "r"(addr));
}
__device__ __forceinline__ void mma16816(float* c, const uint32_t* a, uint32_t b0, uint32_t b1) {
    asm volatile("mma.sync.aligned.m16n8k16.row.col.f32.f16.f16.f32 "
                 "{%0,%1,%2,%3}, {%4,%5,%6,%7}, {%8,%9}, {%0,%1,%2,%3};"
                 : "+f"(c[0]), "+f"(c[1]), "+f"(c[2]), "+f"(c[3])
                 : "r"(a[0]), "r"(a[1]), "r"(a[2]), "r"(a[3]), "r"(b0), "r"(b1));
}
__device__ __forceinline__ void split16(float x, __half& h, __half& l) {
    h = __float2half_rn(x);
    l = __float2half_rn(x - __half2float(h));
}
// rho-layout row index for (point p, channel ch)
__device__ __forceinline__ size_t rho(int p, int ch) {
    return (size_t)(p >> 4) * MT + ch * 16 + (p & 15);
}

// ---------- weight prep: W^T split into fp16 hi/lo ----------
__global__ void k_wprep(const float* W1, const float* W2, const float* W3,
                        const float* W4, const float* W5,
                        __half* __restrict__ wh, __half* __restrict__ wl) {
    int L = blockIdx.y, k = blockIdx.x, n = threadIdx.x;
    const float* W = (L == 0) ? W1 : (L == 1) ? W2 : (L == 2) ? W3 : (L == 3) ? W4 : W5;
    float w = W[k * 256 + n];
    __half h, l;
    split16(w, h, l);
    size_t o = (size_t)L * 65536 + (size_t)n * 256 + k;
    wh[o] = h;
    wl[o] = l;
}

// ---------- layer 0: inputs -> activated 5-channel state, rho layout ----------
__global__ void k_init(const float* __restrict__ t, const float* __restrict__ x,
                       const float* __restrict__ y, const float* __restrict__ W0,
                       const float* __restrict__ b0,
                       __half* __restrict__ oh, __half* __restrict__ ol) {
    int i = blockIdx.x, j = threadIdx.x;
    float w0 = W0[j], w1 = W0[256 + j], w2 = W0[512 + j];
    float a = t[i] * w0 + x[i] * w1 + y[i] * w2 + b0[j];
    float s, c;
    sincosf(a, &s, &c);
    float r[NCH] = {s, c * w0, c * w1, c * w2, -s * (w1 * w1 + w2 * w2)};
#pragma unroll
    for (int ch = 0; ch < NCH; ch++) {
        float v = (ch == 0) ? r[ch] : r[ch] * DSC;
        __half h, l;
        split16(v, h, l);
        size_t o = rho(i, ch) * 256 + j;
        oh[o] = h;
        ol[o] = l;
    }
}

// ---------- fused fp16x3 GEMM + activation, in place ----------
__global__ void __launch_bounds__(NTHR, 1)
k_gemm(__half* __restrict__ Sh, __half* __restrict__ Sl,
       const __half* __restrict__ Wh, const __half* __restrict__ Wl,
       const float* __restrict__ b) {
    extern __shared__ char smem[];
    const uint32_t sb = smem_u32(smem);
    const int tid = threadIdx.x, lane = tid & 31, wid = tid >> 5;
    const int mt = blockIdx.x;
    // warps 0-3: rows 0-47 (mi<3); warps 4-7: rows 48-79 (mi<2). One of each per SMSP.
    const int hiW  = wid >> 2;
    const int warpM = hiW ? 48 : 0;
    const int MIW   = hiW ? 2 : 3;
    const int warpN = (wid & 3) * 64;

    const __half* arh = Sh + (size_t)mt * MT * 256;
    const __half* arl = Sl + (size_t)mt * MT * 256;

    auto issue = [&](int c, int buf) {
        uint32_t base = sb + buf * STAGE;
        // A hi/lo: 80 rows x 8 groups x2 = 1280 blocks, 5 iters
#pragma unroll
        for (int i = 0; i < 5; i++) {
            int idx = tid + i * NTHR;
            int m = idx >= 640;
            int rr = idx - (m ? 640 : 0);
            int r = rr >> 3, q = rr & 7;
            const __half* src = m ? arl : arh;
            cp16(base + (m ? ST_AL : ST_AH) + swz(r * 128 + q * 16),
                 src + (size_t)r * 256 + c * 64 + q * 8);
        }
        // W hi/lo: 256 rows x 8 groups x2 = 4096 blocks, 16 iters
#pragma unroll
        for (int i = 0; i < 16; i++) {
            int idx = tid + i * NTHR;
            int m = idx >= 2048;
            int rr = idx & 2047;
            int n = rr >> 3, q = rr & 7;
            const __half* src = m ? Wl : Wh;
            cp16(base + (m ? ST_WL : ST_WH) + swz(n * 128 + q * 16),
                 src + (size_t)n * 256 + c * 64 + q * 8);
        }
        asm volatile("cp.async.commit_group;" ::: "memory");
    };

    float acc[3][8][4];
#pragma unroll
    for (int mi = 0; mi < 3; mi++)
        for (int nj = 0; nj < 8; nj++)
            for (int q = 0; q < 4; q++) acc[mi][nj][q] = 0.f;

    issue(0, 0);
    issue(1, 1);

    const int lr = lane & 7, g = lane >> 3;
    const int roff = (g & 1) * 8 + lr;
    const int koff = (g >> 1) * 16;

    for (int c = 0; c < 4; c++) {
        const int buf = c & 1;
        if (c < 3) asm volatile("cp.async.wait_group 1;" ::: "memory");
        else       asm volatile("cp.async.wait_group 0;" ::: "memory");
        __syncthreads();
        const uint32_t base = sb + buf * STAGE;

#pragma unroll
        for (int ks = 0; ks < 4; ks++) {
            const int kb = ks * 32 + koff;
            uint32_t a_hi[3][4], a_lo[3][4], bq[4][4];
#pragma unroll
            for (int p = 0; p < 4; p++)
                ldsm4(bq[p], base + ST_WH + swz((warpN + p * 16 + roff) * 128 + kb));
#pragma unroll
            for (int mi = 0; mi < 3; mi++)
                if (mi < MIW)
                    ldsm4(a_hi[mi], base + ST_AH + swz((warpM + mi * 16 + roff) * 128 + kb));
            // main: hi*hi
#pragma unroll
            for (int mi = 0; mi < 3; mi++)
                if (mi < MIW)
#pragma unroll
                    for (int p = 0; p < 4; p++) {
                        mma16816(acc[mi][2 * p],     a_hi[mi], bq[p][0], bq[p][2]);
                        mma16816(acc[mi][2 * p + 1], a_hi[mi], bq[p][1], bq[p][3]);
                    }
            // lo*hi
#pragma unroll
            for (int mi = 0; mi < 3; mi++)
                if (mi < MIW)
                    ldsm4(a_lo[mi], base + ST_AL + swz((warpM + mi * 16 + roff) * 128 + kb));
#pragma unroll
            for (int mi = 0; mi < 3; mi++)
                if (mi < MIW)
#pragma unroll
                    for (int p = 0; p < 4; p++) {
                        mma16816(acc[mi][2 * p],     a_lo[mi], bq[p][0], bq[p][2]);
                        mma16816(acc[mi][2 * p + 1], a_lo[mi], bq[p][1], bq[p][3]);
                    }
            // hi*lo
#pragma unroll
            for (int p = 0; p < 4; p++)
                ldsm4(bq[p], base + ST_WL + swz((warpN + p * 16 + roff) * 128 + kb));
#pragma unroll
            for (int mi = 0; mi < 3; mi++)
                if (mi < MIW)
#pragma unroll
                    for (int p = 0; p < 4; p++) {
                        mma16816(acc[mi][2 * p],     a_hi[mi], bq[p][0], bq[p][2]);
                        mma16816(acc[mi][2 * p + 1], a_hi[mi], bq[p][1], bq[p][3]);
                    }
        }
        __syncthreads();
        if (c + 2 < 4) issue(c + 2, buf);
    }

    // ---- fused epilogue: stage Z, apply bias + sin chain rule (5-ch), store in place ----
    float* Zs = (float*)smem;                         // 80 x ZS_LD fp32 = 84480 B
    const int qr = lane >> 2, qc = (lane & 3) * 2;
#pragma unroll
    for (int mi = 0; mi < 3; mi++) {
        if (mi < MIW) {
            const int r0 = warpM + mi * 16 + qr;
#pragma unroll
            for (int nj = 0; nj < 8; nj++) {
                const int col = warpN + nj * 8 + qc;
                *(float2*)(Zs + (size_t)r0 * ZS_LD + col) =
                    make_float2(acc[mi][nj][0], acc[mi][nj][1]);
                *(float2*)(Zs + (size_t)(r0 + 8) * ZS_LD + col) =
                    make_float2(acc[mi][nj][2], acc[mi][nj][3]);
            }
        }
    }
    __syncthreads();

    const int j = tid;
    const float bj = __ldg(b + j);
    const size_t g0 = (size_t)mt * MT;
#pragma unroll 4
    for (int pl = 0; pl < 16; pl++) {
        float a0 = Zs[(0 * 16 + pl) * ZS_LD + j] + bj;
        float a1 = Zs[(1 * 16 + pl) * ZS_LD + j] * DSCI;   // t
        float a2 = Zs[(2 * 16 + pl) * ZS_LD + j] * DSCI;   // x
        float a3 = Zs[(3 * 16 + pl) * ZS_LD + j] * DSCI;   // y
        float a4 = Zs[(4 * 16 + pl) * ZS_LD + j] * DSCI;   // Laplacian
        float s, c;
        sincosf(a0, &s, &c);
        float r[NCH] = {s, c * a1, c * a2, c * a3,
                        c * a4 - s * (a2 * a2 + a3 * a3)};
#pragma unroll
        for (int ch = 0; ch < NCH; ch++) {
            float v = (ch == 0) ? r[ch] : r[ch] * DSC;
            __half h, l;
            split16(v, h, l);
            size_t o = (g0 + ch * 16 + pl) * 256 + j;
            Sh[o] = h;
            Sl[o] = l;
        }
    }
}

// ---------- final layer (256->3) + NS residuals, 5-channel ----------
__global__ void k_final(const __half* __restrict__ ih, const __half* __restrict__ il,
                        const float* __restrict__ W6, const float* __restrict__ b6,
                        float* __restrict__ out) {
    const int warp = (blockIdx.x * blockDim.x + threadIdx.x) >> 5;
    const int lane = threadIdx.x & 31;
    if (warp >= NPTS) return;
    float acc[NCH][3];
#pragma unroll
    for (int ch = 0; ch < NCH; ch++)
        for (int o = 0; o < 3; o++) acc[ch][o] = 0.f;
    for (int k = lane; k < HID; k += 32) {
        float w0 = W6[k * 3], w1 = W6[k * 3 + 1], w2 = W6[k * 3 + 2];
#pragma unroll
        for (int ch = 0; ch < NCH; ch++) {
            size_t o = rho(warp, ch) * 256 + k;
            float h = __half2float(ih[o]) + __half2float(il[o]);
            acc[ch][0] += h * w0; acc[ch][1] += h * w1; acc[ch][2] += h * w2;
        }
    }
#pragma unroll
    for (int ch = 0; ch < NCH; ch++)
        for (int o = 0; o < 3; o++)
            for (int off = 16; off; off >>= 1)
                acc[ch][o] += __shfl_xor_sync(0xFFFFFFFFu, acc[ch][o], off);
    if (lane == 0) {
        float u = acc[0][0] + b6[0], v = acc[0][1] + b6[1];
        float ut = acc[1][0] * DSCI, vt = acc[1][1] * DSCI;
        float ux = acc[2][0] * DSCI, vx = acc[2][1] * DSCI, px = acc[2][2] * DSCI;
        float uy = acc[3][0] * DSCI, vy = acc[3][1] * DSCI, py = acc[3][2] * DSCI;
        float lapU = acc[4][0] * DSCI, lapV = acc[4][1] * DSCI;
        out[0 * NPTS + warp] = ut + (u * ux + v * uy) + px - NUF * lapU;
        out[1 * NPTS + warp] = vt + (u * vx + v * vy) + py - NUF * lapV;
        out[2 * NPTS + warp] = ux + vy;
    }
}

extern "C" void kernel_launch(void* const* d_in, const int* in_sizes, int n_in,
                              void* d_out, int out_size) {
    const float* t  = (const float*)d_in[0];
    const float* x  = (const float*)d_in[1];
    const float* y  = (const float*)d_in[2];
    const float* W0 = (const float*)d_in[3];
    const float* b0 = (const float*)d_in[4];
    const float* Wm[5] = {(const float*)d_in[5], (const float*)d_in[7], (const float*)d_in[9],
                          (const float*)d_in[11], (const float*)d_in[13]};
    const float* bm[5] = {(const float*)d_in[6], (const float*)d_in[8], (const float*)d_in[10],
                          (const float*)d_in[12], (const float*)d_in[14]};
    const float* W6 = (const float*)d_in[15];
    const float* b6 = (const float*)d_in[16];
    float* out = (float*)d_out;

    __half *sh, *sl, *wh, *wl;
    cudaGetSymbolAddress((void**)&sh, g_sh);
    cudaGetSymbolAddress((void**)&sl, g_sl);
    cudaGetSymbolAddress((void**)&wh, g_wh);
    cudaGetSymbolAddress((void**)&wl, g_wl);
    cudaFuncSetAttribute(k_gemm, cudaFuncAttributeMaxDynamicSharedMemorySize, SMEM_BYTES);

    k_wprep<<<dim3(256, 5), 256>>>(Wm[0], Wm[1], Wm[2], Wm[3], Wm[4], wh, wl);
    k_init<<<NPTS, 256>>>(t, x, y, W0, b0, sh, sl);
    for (int L = 0; L < 5; L++) {
        k_gemm<<<GRID_M, NTHR, SMEM_BYTES>>>(sh, sl, wh + (size_t)L * 65536,
                                             wl + (size_t)L * 65536, bm[L]);
    }
    k_final<<<NPTS / 8, 256>>>(sh, sl, W6, b6, out);
}